// round 14
// baseline (speedup 1.0000x reference)
#include <cuda_runtime.h>
#include <cuda_bf16.h>
#include <cstdint>

typedef unsigned long long u64;

// Problem constants
#define NB 4
#define NS 2048
#define ND 1024
#define NH 16
#define NDK 64
#define NM (NB * NS)   // 8192 rows

// ---------------------------------------------------------------------------
// Scratch (device globals: allocation-free)
// ---------------------------------------------------------------------------
__device__ __align__(16) __nv_bfloat16 g_Ahi[3 * NM * ND];
__device__ __align__(16) __nv_bfloat16 g_Alo[3 * NM * ND];
__device__ __align__(16) __nv_bfloat16 g_Whi[4 * ND * ND];
__device__ __align__(16) __nv_bfloat16 g_Wlo[4 * ND * ND];
__device__ __align__(16) __nv_bfloat16 g_Qhi[NB * NH * NS * NDK];  // [B,H,S,dk]
__device__ __align__(16) __nv_bfloat16 g_Qlo[NB * NH * NS * NDK];
__device__ __align__(16) __nv_bfloat16 g_Khi[NB * NH * NS * NDK];
__device__ __align__(16) __nv_bfloat16 g_Klo[NB * NH * NS * NDK];
__device__ __align__(16) __nv_bfloat16 g_Vhi[NB * NH * NS * NDK];
__device__ __align__(16) __nv_bfloat16 g_Vlo[NB * NH * NS * NDK];
__device__ __align__(16) u64 g_maskbits[NS * NS / 64];    // bit-packed mask
__device__ int g_tile_counter;                            // persistent-flash work queue

// ---------------------------------------------------------------------------
// Helpers
// ---------------------------------------------------------------------------
__device__ __forceinline__ uint32_t smem_u32(const void* p) {
    uint32_t a;
    asm("{ .reg .u64 t; cvta.to.shared.u64 t, %1; cvt.u32.u64 %0, t; }" : "=r"(a) : "l"(p));
    return a;
}
#define SW128(bo) ((bo) ^ (((bo) >> 3) & 0x70))

__device__ __forceinline__ void ldm_x4(uint32_t& r0, uint32_t& r1, uint32_t& r2,
                                       uint32_t& r3, uint32_t addr) {
    asm volatile("ldmatrix.sync.aligned.m8n8.x4.shared.b16 {%0,%1,%2,%3}, [%4];"
                 : "=r"(r0), "=r"(r1), "=r"(r2), "=r"(r3) : "r"(addr));
}
__device__ __forceinline__ void ldm_x4t(uint32_t& r0, uint32_t& r1, uint32_t& r2,
                                        uint32_t& r3, uint32_t addr) {
    asm volatile("ldmatrix.sync.aligned.m8n8.x4.trans.shared.b16 {%0,%1,%2,%3}, [%4];"
                 : "=r"(r0), "=r"(r1), "=r"(r2), "=r"(r3) : "r"(addr));
}
__device__ __forceinline__ void mma16816(float* d, const uint32_t* a, const uint32_t* b) {
    asm volatile("mma.sync.aligned.m16n8k16.row.col.f32.bf16.bf16.f32 "
                 "{%0,%1,%2,%3}, {%4,%5,%6,%7}, {%8,%9}, {%0,%1,%2,%3};"
                 : "+f"(d[0]), "+f"(d[1]), "+f"(d[2]), "+f"(d[3])
                 : "r"(a[0]), "r"(a[1]), "r"(a[2]), "r"(a[3]), "r"(b[0]), "r"(b[1]));
}

__device__ __forceinline__ void cp_async16(uint32_t s, const void* g) {
    asm volatile("{ .reg .u64 gg; cvta.to.global.u64 gg, %1; "
                 "cp.async.cg.shared.global [%0], [gg], 16; }"
                 :: "r"(s), "l"(g) : "memory");
}
#define CP_COMMIT() asm volatile("cp.async.commit_group;" ::: "memory")
#define CP_WAIT1()  asm volatile("cp.async.wait_group 1;" ::: "memory")
#define CP_WAIT0()  asm volatile("cp.async.wait_group 0;" ::: "memory")

__device__ __forceinline__ float ex2f(float x) {
    float r;
    asm("ex2.approx.f32 %0, %1;" : "=f"(r) : "f"(x));
    return r;
}

// split fp32 pair -> packed bf16 hi pair + bf16 residual pair
__device__ __forceinline__ void split_pair(float a, float b, uint32_t& hi, uint32_t& lo) {
    __nv_bfloat16 ha = __float2bfloat16(a), hb = __float2bfloat16(b);
    __nv_bfloat16 la = __float2bfloat16(a - __bfloat162float(ha));
    __nv_bfloat16 lb = __float2bfloat16(b - __bfloat162float(hb));
    __nv_bfloat162 H(ha, hb), L(la, lb);
    hi = *reinterpret_cast<uint32_t*>(&H);
    lo = *reinterpret_cast<uint32_t*>(&L);
}

// ---------------------------------------------------------------------------
// Preprocess kernels
// ---------------------------------------------------------------------------
__global__ void reset_counter(void) { g_tile_counter = 0; }

// fused: grid.y = slot (0..2)
__global__ __launch_bounds__(256) void split_act(
    const float* __restrict__ a0, const float* __restrict__ a1,
    const float* __restrict__ a2)
{
    int slot = blockIdx.y;
    const float* src = (slot == 0) ? a0 : (slot == 1) ? a1 : a2;
    size_t base = (size_t)slot * NM * ND;
    int i = (blockIdx.x * 256 + threadIdx.x) * 4;
    float4 v = *(const float4*)(src + i);
    uint32_t h0, l0, h1, l1;
    split_pair(v.x, v.y, h0, l0);
    split_pair(v.z, v.w, h1, l1);
    *(uint32_t*)(g_Ahi + base + i) = h0; *(uint32_t*)(g_Ahi + base + i + 2) = h1;
    *(uint32_t*)(g_Alo + base + i) = l0; *(uint32_t*)(g_Alo + base + i + 2) = l1;
}

// fused: grid.y = slot (0..3)
__global__ __launch_bounds__(256) void split_wgt(
    const float* __restrict__ w0, const float* __restrict__ w1,
    const float* __restrict__ w2, const float* __restrict__ w3)
{
    int slot = blockIdx.y;
    const float* src = (slot == 0) ? w0 : (slot == 1) ? w1 : (slot == 2) ? w2 : w3;
    size_t base = (size_t)slot * ND * ND;
    int i = (blockIdx.x * 256 + threadIdx.x) * 4;
    float4 v = *(const float4*)(src + i);
    uint32_t h0, l0, h1, l1;
    split_pair(v.x, v.y, h0, l0);
    split_pair(v.z, v.w, h1, l1);
    *(uint32_t*)(g_Whi + base + i) = h0; *(uint32_t*)(g_Whi + base + i + 2) = h1;
    *(uint32_t*)(g_Wlo + base + i) = l0; *(uint32_t*)(g_Wlo + base + i + 2) = l1;
}

// mask int32[S][S] -> bitmap u64[S][S/64]
__global__ __launch_bounds__(256) void mask_pack(const int* __restrict__ mask)
{
    int w = blockIdx.x * 256 + threadIdx.x;     // 0 .. 65535
    const int4* src = (const int4*)(mask + (size_t)w * 64);
    u64 bits = 0;
#pragma unroll
    for (int q = 0; q < 16; q++) {
        int4 v = src[q];
        bits |= ((u64)(v.x != 0) << (q * 4 + 0)) | ((u64)(v.y != 0) << (q * 4 + 1))
              | ((u64)(v.z != 0) << (q * 4 + 2)) | ((u64)(v.w != 0) << (q * 4 + 3));
    }
    g_maskbits[w] = bits;
}

// ---------------------------------------------------------------------------
// mma.sync GEMM, 3-stage cp.async pipeline, ONE barrier per K-chunk.
// 512 threads / 16 warps; warp grid 4(m) x 4(n): warp tile 32x32. (proven)
// ---------------------------------------------------------------------------
#define GOFF_AHI 0
#define GOFF_ALO 16384
#define GOFF_WHI 32768
#define GOFF_WLO 49152
#define GSTAGE   65536
#define GEMM_SMEM (3 * GSTAGE)   // 196608

__global__ __launch_bounds__(512) void gemm_tc(
    const float* __restrict__ bias0, const float* __restrict__ bias1,
    const float* __restrict__ bias2, float* __restrict__ Cp, int base_mode)
{
    extern __shared__ __align__(1024) char smem[];
    const uint32_t sb = smem_u32(smem);
    const int tid = threadIdx.x;
    const int wid = tid >> 5;
    const int lane = tid & 31;
    const int wm = wid >> 2;
    const int wn = wid & 3;
    const int bm = blockIdx.y * 128;
    const int bn = blockIdx.x * 128;
    const int z = blockIdx.z;
    const int mode = (base_mode == 0) ? 0 : 1 + z;
    const float* bias = (z == 0) ? bias0 : (z == 1) ? bias1 : bias2;

    const int aslot = (mode == 0) ? 0 : mode - 1;
    const int wslot = (mode == 0) ? 3 : mode - 1;
    const __nv_bfloat16* Ahi = g_Ahi + (size_t)aslot * NM * ND;
    const __nv_bfloat16* Alo = g_Alo + (size_t)aslot * NM * ND;
    const __nv_bfloat16* Whi = g_Whi + (size_t)wslot * ND * ND;
    const __nv_bfloat16* Wlo = g_Wlo + (size_t)wslot * ND * ND;

    const __nv_bfloat16* srcs[4] = {Ahi, Alo, Whi, Wlo};
    const int row0[4] = {bm, bm, bn, bn};
    const uint32_t toff[4] = {GOFF_AHI, GOFF_ALO, GOFF_WHI, GOFF_WLO};

    float acc[2][4][4];
#pragma unroll
    for (int mi = 0; mi < 2; mi++)
#pragma unroll
        for (int c = 0; c < 4; c++)
#pragma unroll
            for (int t = 0; t < 4; t++) acc[mi][c][t] = 0.f;

    const uint32_t aRow = (uint32_t)(wm * 32 + (lane & 15));
    const uint32_t aKb  = (uint32_t)((lane >> 4) << 4);
    const uint32_t bRow = (uint32_t)(wn * 32 + (lane & 7) + ((lane >> 4) & 1) * 8);
    const uint32_t bKb  = (uint32_t)(((lane >> 3) & 1) << 4);

    auto load_stage = [&](int kc) {
        const int k0 = kc * 64;
        const uint32_t sbase = sb + (uint32_t)((kc % 3) * GSTAGE);
#pragma unroll
        for (int t = 0; t < 4; t++) {
#pragma unroll
            for (int u = 0; u < 2; u++) {
                int idx = u * 512 + tid;
                int r = idx >> 3, c = idx & 7;
                uint32_t bo = (uint32_t)(r * 128 + c * 16);
                cp_async16(sbase + toff[t] + SW128(bo),
                           srcs[t] + (size_t)(row0[t] + r) * ND + k0 + c * 8);
            }
        }
    };

    load_stage(0); CP_COMMIT();
    load_stage(1); CP_COMMIT();

    for (int kc = 0; kc < 16; kc++) {
        if (kc < 14) CP_WAIT1(); else CP_WAIT0();
        __syncthreads();                   // publishes stage kc; frees buf (kc+2)%3
        if (kc < 14) { load_stage(kc + 2); CP_COMMIT(); }

        const uint32_t stage = sb + (uint32_t)((kc % 3) * GSTAGE);
#pragma unroll
        for (int ks = 0; ks < 4; ks++) {
            uint32_t ah[2][4], al[2][4];
#pragma unroll
            for (int mi = 0; mi < 2; mi++) {
                uint32_t off = SW128((aRow + mi * 16) * 128 + (uint32_t)(ks * 32) + aKb);
                ldm_x4(ah[mi][0], ah[mi][1], ah[mi][2], ah[mi][3], stage + GOFF_AHI + off);
                ldm_x4(al[mi][0], al[mi][1], al[mi][2], al[mi][3], stage + GOFF_ALO + off);
            }
            uint32_t bh[2][4], bl[2][4];
#pragma unroll
            for (int nj = 0; nj < 2; nj++) {
                uint32_t off = SW128((bRow + nj * 16) * 128 + (uint32_t)(ks * 32) + bKb);
                ldm_x4(bh[nj][0], bh[nj][1], bh[nj][2], bh[nj][3], stage + GOFF_WHI + off);
                ldm_x4(bl[nj][0], bl[nj][1], bl[nj][2], bl[nj][3], stage + GOFF_WLO + off);
            }
#pragma unroll
            for (int mi = 0; mi < 2; mi++)
#pragma unroll
                for (int nj = 0; nj < 2; nj++) {
                    mma16816(acc[mi][nj * 2 + 0], ah[mi], &bh[nj][0]);
                    mma16816(acc[mi][nj * 2 + 1], ah[mi], &bh[nj][2]);
                }
#pragma unroll
            for (int mi = 0; mi < 2; mi++)
#pragma unroll
                for (int nj = 0; nj < 2; nj++) {
                    mma16816(acc[mi][nj * 2 + 0], al[mi], &bh[nj][0]);
                    mma16816(acc[mi][nj * 2 + 1], al[mi], &bh[nj][2]);
                }
#pragma unroll
            for (int mi = 0; mi < 2; mi++)
#pragma unroll
                for (int nj = 0; nj < 2; nj++) {
                    mma16816(acc[mi][nj * 2 + 0], ah[mi], &bl[nj][0]);
                    mma16816(acc[mi][nj * 2 + 1], ah[mi], &bl[nj][2]);
                }
        }
    }

    // Epilogue
    __nv_bfloat16 *dHi = nullptr, *dLo = nullptr;
    if (mode == 1) { dHi = g_Qhi; dLo = g_Qlo; }
    else if (mode == 2) { dHi = g_Khi; dLo = g_Klo; }
    else if (mode == 3) { dHi = g_Vhi; dLo = g_Vlo; }

    const int g = lane >> 2, tg = lane & 3;
#pragma unroll
    for (int mi = 0; mi < 2; mi++) {
#pragma unroll
        for (int c = 0; c < 4; c++) {
            int n = bn + wn * 32 + c * 8 + tg * 2;
            float bx = bias[n], by = bias[n + 1];
            int m0 = bm + wm * 32 + mi * 16 + g;
#pragma unroll
            for (int half = 0; half < 2; half++) {
                int m = m0 + half * 8;
                float ox = acc[mi][c][half * 2 + 0] + bx;
                float oy = acc[mi][c][half * 2 + 1] + by;
                if (mode == 0) {
                    *(float2*)(Cp + (size_t)m * ND + n) = make_float2(ox, oy);
                } else {
                    int bb = m >> 11, ss = m & 2047;
                    int h = n >> 6, dd = n & 63;
                    size_t idx = (((size_t)(bb * NH + h) * NS + ss) * NDK) + dd;
                    uint32_t hi, lo;
                    split_pair(ox, oy, hi, lo);
                    *(uint32_t*)(dHi + idx) = hi;
                    *(uint32_t*)(dLo + idx) = lo;
                }
            }
        }
    }
}

// ---------------------------------------------------------------------------
// PERSISTENT flash attention, KV-SPLIT across warps.
// 148 CTAs x 512 threads (16 warps/SM): warp grid 8(m) x 2(kv).
// Warp tile: m16 x kv32 for QK; kv32-partial m16 x d64 for PV.
// LDSM per SM per KV tile drops 1152 -> 640 ldm.x4 (tensor now dominant).
// Cross-warp (kv-half) reduction of o and lsum done ONCE per tile via smem
// (valid because fixed-max softmax needs no per-iteration row state).
// Smem: Qhi/Qlo 32KB + 2 KV stages x 32KB = 96KB; stage area reused as the
// 32KB fp32 o-exchange buffer + row-sum buffer in the epilogue.
// ---------------------------------------------------------------------------
#define FQHI 0
#define FQLO 16384
#define FSTG 32768
#define FKHI 0
#define FKLO 8192
#define FVHI 16384
#define FVLO 24576
#define FLASH_SMEM (32768 + 2 * 32768)   // 98304
#define N_TILES (NB * NH * (NS / 128))   // 1024

#define EXP_K2 0.18033688011112042f     // 0.125 * log2(e)
#define EXP_C2 23.083120654223414f      // 16 * log2(e)

__global__ __launch_bounds__(512) void flash_mma(void)
{
    extern __shared__ __align__(1024) char fsm[];
    __shared__ int s_tile;
    const uint32_t sb = smem_u32(fsm);
    const int tid = threadIdx.x;
    const int wid = tid >> 5;
    const int lane = tid & 31;
    const int g = lane >> 2, tg = lane & 3;
    const int wm = wid & 7;      // m16 row group (0..7)
    const int wg = wid >> 3;     // kv half (0..1)

    // fragment address components
    const uint32_t aRow = (uint32_t)(wm * 16 + (lane & 15));
    const uint32_t aKb  = (uint32_t)((lane >> 4) << 4);
    const uint32_t bRow = (uint32_t)(wg * 32 + (lane & 7) + ((lane >> 4) & 1) * 8);
    const uint32_t bKb  = (uint32_t)(((lane >> 3) & 1) << 4);
    const uint32_t vRow = (uint32_t)(wg * 32 + (lane & 7) + ((lane >> 3) & 1) * 8); // trans
    const uint32_t vNb  = (uint32_t)(((lane >> 4) & 1) << 4);

    for (;;) {
        __syncthreads();   // prior tile fully consumed (smem + redbuf safe)
        if (tid == 0) s_tile = atomicAdd(&g_tile_counter, 1);
        __syncthreads();
        const int t = s_tile;
        if (t >= N_TILES) break;

        const int qt = t & 15;
        const int h  = (t >> 4) & 15;
        const int b  = t >> 8;

        const size_t kvbase = (size_t)(b * NH + h) * NS * NDK;
        const size_t qbase  = kvbase + (size_t)qt * 128 * NDK;

        // Q tile (128 rows) + first KV stage
#pragma unroll
        for (int u = 0; u < 2; u++) {
            int idx = u * 512 + tid;
            int r = idx >> 3, c = idx & 7;
            uint32_t bo = SW128((uint32_t)(r * 128 + c * 16));
            size_t go = qbase + (size_t)r * NDK + c * 8;
            cp_async16(sb + FQHI + bo, g_Qhi + go);
            cp_async16(sb + FQLO + bo, g_Qlo + go);
        }
        {
            int r = tid >> 3, c = tid & 7;     // 512 thr = 64 rows x 8 cols
            uint32_t bo = SW128((uint32_t)(r * 128 + c * 16));
            size_t go = kvbase + (size_t)r * NDK + c * 8;
            cp_async16(sb + FSTG + FKHI + bo, g_Khi + go);
            cp_async16(sb + FSTG + FKLO + bo, g_Klo + go);
            cp_async16(sb + FSTG + FVHI + bo, g_Vhi + go);
            cp_async16(sb + FSTG + FVLO + bo, g_Vlo + go);
        }
        CP_COMMIT();

        float o[8][4];                     // m16 x d64 partial (kv half)
#pragma unroll
        for (int nj = 0; nj < 8; nj++)
#pragma unroll
            for (int tt = 0; tt < 4; tt++) o[nj][tt] = 0.f;
        float lsum0 = 0.f, lsum1 = 0.f;    // partial row sums (kv half)
        const int qg0 = qt * 128 + wm * 16 + g;

        for (int kt = 0; kt < NS / 64; kt++) {
            CP_WAIT0();
            __syncthreads();             // publishes stage kt; frees buf (kt+1)&1
            if (kt < NS / 64 - 1) {
                uint32_t sbase = sb + FSTG + (uint32_t)(((kt + 1) & 1) * 32768);
                int r = tid >> 3, c = tid & 7;
                uint32_t bo = SW128((uint32_t)(r * 128 + c * 16));
                size_t go = kvbase + (size_t)((kt + 1) * 64 + r) * NDK + c * 8;
                cp_async16(sbase + FKHI + bo, g_Khi + go);
                cp_async16(sbase + FKLO + bo, g_Klo + go);
                cp_async16(sbase + FVHI + bo, g_Vhi + go);
                cp_async16(sbase + FVLO + bo, g_Vlo + go);
                CP_COMMIT();
            }

            const uint32_t st = sb + FSTG + (uint32_t)((kt & 1) * 32768);

            // QK^T: sc[nj 0..3][4] for this warp's kv32 half
            float sc[4][4];
#pragma unroll
            for (int nj = 0; nj < 4; nj++)
#pragma unroll
                for (int tt = 0; tt < 4; tt++) sc[nj][tt] = 0.f;

#pragma unroll
            for (int kk = 0; kk < 4; kk++) {
                uint32_t qh4[4], ql4[4];
                uint32_t qo = SW128(aRow * 128 + (uint32_t)(kk * 32) + aKb);
                ldm_x4(qh4[0], qh4[1], qh4[2], qh4[3], sb + FQHI + qo);
                ldm_x4(ql4[0], ql4[1], ql4[2], ql4[3], sb + FQLO + qo);
#pragma unroll
                for (int njl = 0; njl < 2; njl++) {
                    uint32_t bo = SW128((bRow + njl * 16) * 128 + (uint32_t)(kk * 32) + bKb);
                    uint32_t bh4[4], bl4[4];
                    ldm_x4(bh4[0], bh4[1], bh4[2], bh4[3], st + FKHI + bo);
                    ldm_x4(bl4[0], bl4[1], bl4[2], bl4[3], st + FKLO + bo);
                    mma16816(sc[2 * njl + 0], qh4, &bh4[0]);
                    mma16816(sc[2 * njl + 1], qh4, &bh4[2]);
                    mma16816(sc[2 * njl + 0], ql4, &bh4[0]);
                    mma16816(sc[2 * njl + 1], ql4, &bh4[2]);
                    mma16816(sc[2 * njl + 0], qh4, &bl4[0]);
                    mma16816(sc[2 * njl + 1], qh4, &bl4[2]);
                }
            }

            // mask (bitmap, this warp's 32-bit half) + fixed-max exp2 softmax
            uint2 w0 = *(const uint2*)(g_maskbits + (size_t)qg0 * 32 + kt);
            uint2 w1 = *(const uint2*)(g_maskbits + (size_t)(qg0 + 8) * 32 + kt);
            unsigned m0w = wg ? w0.y : w0.x;
            unsigned m1w = wg ? w1.y : w1.x;
            float rs0 = 0.f, rs1 = 0.f;
#pragma unroll
            for (int nj = 0; nj < 4; nj++) {
                int sh = nj * 8 + tg * 2;
                unsigned b0 = m0w >> sh, b1 = m1w >> sh;
                float p0 = ex2f((b0 & 1) ? fmaf(sc[nj][0], EXP_K2, -EXP_C2) : -1e9f);
                float p1 = ex2f((b0 & 2) ? fmaf(sc[nj][1], EXP_K2, -EXP_C2) : -1e9f);
                float p2 = ex2f((b1 & 1) ? fmaf(sc[nj][2], EXP_K2, -EXP_C2) : -1e9f);
                float p3 = ex2f((b1 & 2) ? fmaf(sc[nj][3], EXP_K2, -EXP_C2) : -1e9f);
                sc[nj][0] = p0; sc[nj][1] = p1;
                sc[nj][2] = p2; sc[nj][3] = p3;
                rs0 += p0 + p1;
                rs1 += p2 + p3;
            }
            rs0 += __shfl_xor_sync(0xffffffffu, rs0, 1);
            rs0 += __shfl_xor_sync(0xffffffffu, rs0, 2);
            rs1 += __shfl_xor_sync(0xffffffffu, rs1, 1);
            rs1 += __shfl_xor_sync(0xffffffffu, rs1, 2);
            lsum0 += rs0;
            lsum1 += rs1;

            // P*V over this warp's kv32 (2 kv16 steps)
#pragma unroll
            for (int kk2 = 0; kk2 < 2; kk2++) {
                uint32_t ph[4], pl[4];
                split_pair(sc[2 * kk2][0],     sc[2 * kk2][1],     ph[0], pl[0]);
                split_pair(sc[2 * kk2][2],     sc[2 * kk2][3],     ph[1], pl[1]);
                split_pair(sc[2 * kk2 + 1][0], sc[2 * kk2 + 1][1], ph[2], pl[2]);
                split_pair(sc[2 * kk2 + 1][2], sc[2 * kk2 + 1][3], ph[3], pl[3]);
#pragma unroll
                for (int njp = 0; njp < 4; njp++) {
                    uint32_t bo = SW128((uint32_t)(kk2 * 16 + vRow) * 128 +
                                        (uint32_t)(njp * 32) + vNb);
                    uint32_t vh4[4], vl4[4];
                    ldm_x4t(vh4[0], vh4[1], vh4[2], vh4[3], st + FVHI + bo);
                    ldm_x4t(vl4[0], vl4[1], vl4[2], vl4[3], st + FVLO + bo);
                    mma16816(o[2 * njp + 0], ph, &vh4[0]);
                    mma16816(o[2 * njp + 1], ph, &vh4[2]);
                    mma16816(o[2 * njp + 0], pl, &vh4[0]);
                    mma16816(o[2 * njp + 1], pl, &vh4[2]);
                    mma16816(o[2 * njp + 0], ph, &vl4[0]);
                    mma16816(o[2 * njp + 1], ph, &vl4[2]);
                }
            }
        }

        // Epilogue: cross-warp (kv half) reduction via smem, then write output.
        __syncthreads();   // all reads of KV stage smem done -> safe to reuse
        float* redbuf = (float*)(fsm + FSTG);            // 128 x 64 fp32 = 32KB
        float* lsbuf  = (float*)(fsm + FSTG + 32768);    // 128 fp32
        const int rl0 = wm * 16 + g;
        if (wg == 0) {
#pragma unroll
            for (int nj = 0; nj < 8; nj++) {
                int col = nj * 8 + tg * 2;
                *(float2*)&redbuf[(rl0)     * 64 + col] = make_float2(o[nj][0], o[nj][1]);
                *(float2*)&redbuf[(rl0 + 8) * 64 + col] = make_float2(o[nj][2], o[nj][3]);
            }
            if (tg == 0) { lsbuf[rl0] = lsum0; lsbuf[rl0 + 8] = lsum1; }
        }
        __syncthreads();
        if (wg == 1) {
            float inv0 = 1.f / (lsum0 + lsbuf[rl0]);
            float inv1 = 1.f / (lsum1 + lsbuf[rl0 + 8]);
            const size_t row0 = (size_t)(b * NS + qg0) * ND;
            const size_t row1 = row0 + (size_t)8 * ND;
#pragma unroll
            for (int nj = 0; nj < 8; nj++) {
                int col = nj * 8 + tg * 2;
                float2 p0 = *(float2*)&redbuf[(rl0)     * 64 + col];
                float2 p1 = *(float2*)&redbuf[(rl0 + 8) * 64 + col];
                int gcol = h * NDK + col;
                uint32_t hi, lo;
                split_pair((o[nj][0] + p0.x) * inv0, (o[nj][1] + p0.y) * inv0, hi, lo);
                *(uint32_t*)(g_Ahi + row0 + gcol) = hi;
                *(uint32_t*)(g_Alo + row0 + gcol) = lo;
                split_pair((o[nj][2] + p1.x) * inv1, (o[nj][3] + p1.y) * inv1, hi, lo);
                *(uint32_t*)(g_Ahi + row1 + gcol) = hi;
                *(uint32_t*)(g_Alo + row1 + gcol) = lo;
            }
        }
    }
}

// ---------------------------------------------------------------------------
extern "C" void kernel_launch(void* const* d_in, const int* in_sizes, int n_in,
                              void* d_out, int out_size)
{
    const float* q    = (const float*)d_in[0];
    const float* k    = (const float*)d_in[1];
    const float* v    = (const float*)d_in[2];
    const int*   mask = (const int*)d_in[3];
    const float* w_q  = (const float*)d_in[4];
    const float* b_q  = (const float*)d_in[5];
    const float* w_k  = (const float*)d_in[6];
    const float* b_k  = (const float*)d_in[7];
    const float* w_v  = (const float*)d_in[8];
    const float* b_v  = (const float*)d_in[9];
    const float* w_o  = (const float*)d_in[10];
    const float* b_o  = (const float*)d_in[11];

    cudaFuncSetAttribute(gemm_tc, cudaFuncAttributeMaxDynamicSharedMemorySize, GEMM_SMEM);
    cudaFuncSetAttribute(flash_mma, cudaFuncAttributeMaxDynamicSharedMemorySize, FLASH_SMEM);

    const int actBlocks = NM * ND / (4 * 256);  // 8192
    const int wBlocks   = ND * ND / (4 * 256);  // 1024

    mask_pack<<<NS * NS / 64 / 256, 256>>>(mask);
    reset_counter<<<1, 1>>>();

    dim3 agrid_s(actBlocks, 3);
    split_act<<<agrid_s, 256>>>(q, k, v);
    dim3 wgrid(wBlocks, 4);
    split_wgt<<<wgrid, 256>>>(w_q, w_k, w_v, w_o);

    dim3 qkvgrid(ND / 128, NM / 128, 3);        // (8, 64, 3)
    gemm_tc<<<qkvgrid, 512, GEMM_SMEM>>>(b_q, b_k, b_v, nullptr, 1);

    flash_mma<<<148, 512, FLASH_SMEM>>>();      // persistent: 1 CTA/SM, 16 warps

    dim3 ogrid(ND / 128, NM / 128, 1);          // (8, 64)
    gemm_tc<<<ogrid, 512, GEMM_SMEM>>>(b_o, b_o, b_o, (float*)d_out, 0);
}

// round 15
// speedup vs baseline: 1.0399x; 1.0399x over previous
#include <cuda_runtime.h>
#include <cuda_bf16.h>
#include <cstdint>

typedef unsigned long long u64;

// Problem constants
#define NB 4
#define NS 2048
#define ND 1024
#define NH 16
#define NDK 64
#define NM (NB * NS)   // 8192 rows

// ---------------------------------------------------------------------------
// Scratch (device globals: allocation-free)
// ---------------------------------------------------------------------------
__device__ __align__(16) __nv_bfloat16 g_Ahi[3 * NM * ND];
__device__ __align__(16) __nv_bfloat16 g_Alo[3 * NM * ND];
__device__ __align__(16) __nv_bfloat16 g_Whi[4 * ND * ND];
__device__ __align__(16) __nv_bfloat16 g_Wlo[4 * ND * ND];
__device__ __align__(16) __nv_bfloat16 g_Qhi[NB * NH * NS * NDK];  // [B,H,S,dk]
__device__ __align__(16) __nv_bfloat16 g_Qlo[NB * NH * NS * NDK];
__device__ __align__(16) __nv_bfloat16 g_Khi[NB * NH * NS * NDK];
__device__ __align__(16) __nv_bfloat16 g_Klo[NB * NH * NS * NDK];
__device__ __align__(16) __nv_bfloat16 g_Vhi[NB * NH * NS * NDK];
__device__ __align__(16) __nv_bfloat16 g_Vlo[NB * NH * NS * NDK];
__device__ __align__(16) u64 g_maskbits[NS * NS / 64];    // bit-packed mask
__device__ int g_tile_counter;                            // persistent-flash work queue

// ---------------------------------------------------------------------------
// Helpers
// ---------------------------------------------------------------------------
__device__ __forceinline__ uint32_t smem_u32(const void* p) {
    uint32_t a;
    asm("{ .reg .u64 t; cvta.to.shared.u64 t, %1; cvt.u32.u64 %0, t; }" : "=r"(a) : "l"(p));
    return a;
}
#define SW128(bo) ((bo) ^ (((bo) >> 3) & 0x70))

__device__ __forceinline__ void ldm_x4(uint32_t& r0, uint32_t& r1, uint32_t& r2,
                                       uint32_t& r3, uint32_t addr) {
    asm volatile("ldmatrix.sync.aligned.m8n8.x4.shared.b16 {%0,%1,%2,%3}, [%4];"
                 : "=r"(r0), "=r"(r1), "=r"(r2), "=r"(r3) : "r"(addr));
}
__device__ __forceinline__ void ldm_x4t(uint32_t& r0, uint32_t& r1, uint32_t& r2,
                                        uint32_t& r3, uint32_t addr) {
    asm volatile("ldmatrix.sync.aligned.m8n8.x4.trans.shared.b16 {%0,%1,%2,%3}, [%4];"
                 : "=r"(r0), "=r"(r1), "=r"(r2), "=r"(r3) : "r"(addr));
}
__device__ __forceinline__ void mma16816(float* d, const uint32_t* a, const uint32_t* b) {
    asm volatile("mma.sync.aligned.m16n8k16.row.col.f32.bf16.bf16.f32 "
                 "{%0,%1,%2,%3}, {%4,%5,%6,%7}, {%8,%9}, {%0,%1,%2,%3};"
                 : "+f"(d[0]), "+f"(d[1]), "+f"(d[2]), "+f"(d[3])
                 : "r"(a[0]), "r"(a[1]), "r"(a[2]), "r"(a[3]), "r"(b[0]), "r"(b[1]));
}

__device__ __forceinline__ void cp_async16(uint32_t s, const void* g) {
    asm volatile("{ .reg .u64 gg; cvta.to.global.u64 gg, %1; "
                 "cp.async.cg.shared.global [%0], [gg], 16; }"
                 :: "r"(s), "l"(g) : "memory");
}
#define CP_COMMIT() asm volatile("cp.async.commit_group;" ::: "memory")
#define CP_WAIT1()  asm volatile("cp.async.wait_group 1;" ::: "memory")
#define CP_WAIT0()  asm volatile("cp.async.wait_group 0;" ::: "memory")

__device__ __forceinline__ float ex2f(float x) {
    float r;
    asm("ex2.approx.f32 %0, %1;" : "=f"(r) : "f"(x));
    return r;
}

// split fp32 pair -> packed bf16 hi pair + bf16 residual pair
__device__ __forceinline__ void split_pair(float a, float b, uint32_t& hi, uint32_t& lo) {
    __nv_bfloat16 ha = __float2bfloat16(a), hb = __float2bfloat16(b);
    __nv_bfloat16 la = __float2bfloat16(a - __bfloat162float(ha));
    __nv_bfloat16 lb = __float2bfloat16(b - __bfloat162float(hb));
    __nv_bfloat162 H(ha, hb), L(la, lb);
    hi = *reinterpret_cast<uint32_t*>(&H);
    lo = *reinterpret_cast<uint32_t*>(&L);
}

// ---------------------------------------------------------------------------
// Preprocess kernels
// ---------------------------------------------------------------------------
// fused: grid.y = slot (0..2)
__global__ __launch_bounds__(256) void split_act(
    const float* __restrict__ a0, const float* __restrict__ a1,
    const float* __restrict__ a2)
{
    int slot = blockIdx.y;
    const float* src = (slot == 0) ? a0 : (slot == 1) ? a1 : a2;
    size_t base = (size_t)slot * NM * ND;
    int i = (blockIdx.x * 256 + threadIdx.x) * 4;
    float4 v = *(const float4*)(src + i);
    uint32_t h0, l0, h1, l1;
    split_pair(v.x, v.y, h0, l0);
    split_pair(v.z, v.w, h1, l1);
    *(uint32_t*)(g_Ahi + base + i) = h0; *(uint32_t*)(g_Ahi + base + i + 2) = h1;
    *(uint32_t*)(g_Alo + base + i) = l0; *(uint32_t*)(g_Alo + base + i + 2) = l1;
}

// fused: grid.y = slot (0..3)
__global__ __launch_bounds__(256) void split_wgt(
    const float* __restrict__ w0, const float* __restrict__ w1,
    const float* __restrict__ w2, const float* __restrict__ w3)
{
    int slot = blockIdx.y;
    const float* src = (slot == 0) ? w0 : (slot == 1) ? w1 : (slot == 2) ? w2 : w3;
    size_t base = (size_t)slot * ND * ND;
    int i = (blockIdx.x * 256 + threadIdx.x) * 4;
    float4 v = *(const float4*)(src + i);
    uint32_t h0, l0, h1, l1;
    split_pair(v.x, v.y, h0, l0);
    split_pair(v.z, v.w, h1, l1);
    *(uint32_t*)(g_Whi + base + i) = h0; *(uint32_t*)(g_Whi + base + i + 2) = h1;
    *(uint32_t*)(g_Wlo + base + i) = l0; *(uint32_t*)(g_Wlo + base + i + 2) = l1;
}

// mask int32[S][S] -> bitmap u64[S][S/64]; also resets the flash tile counter
__global__ __launch_bounds__(256) void mask_pack(const int* __restrict__ mask)
{
    if (blockIdx.x == 0 && threadIdx.x == 0) g_tile_counter = 0;
    int w = blockIdx.x * 256 + threadIdx.x;     // 0 .. 65535
    const int4* src = (const int4*)(mask + (size_t)w * 64);
    u64 bits = 0;
#pragma unroll
    for (int q = 0; q < 16; q++) {
        int4 v = src[q];
        bits |= ((u64)(v.x != 0) << (q * 4 + 0)) | ((u64)(v.y != 0) << (q * 4 + 1))
              | ((u64)(v.z != 0) << (q * 4 + 2)) | ((u64)(v.w != 0) << (q * 4 + 3));
    }
    g_maskbits[w] = bits;
}

// ---------------------------------------------------------------------------
// mma.sync GEMM, 3-stage cp.async pipeline, ONE barrier per K-chunk.
// 512 threads / 16 warps; warp grid 4(m) x 4(n): warp tile 32x32. (proven)
// ---------------------------------------------------------------------------
#define GOFF_AHI 0
#define GOFF_ALO 16384
#define GOFF_WHI 32768
#define GOFF_WLO 49152
#define GSTAGE   65536
#define GEMM_SMEM (3 * GSTAGE)   // 196608

__global__ __launch_bounds__(512) void gemm_tc(
    const float* __restrict__ bias0, const float* __restrict__ bias1,
    const float* __restrict__ bias2, float* __restrict__ Cp, int base_mode)
{
    extern __shared__ __align__(1024) char smem[];
    const uint32_t sb = smem_u32(smem);
    const int tid = threadIdx.x;
    const int wid = tid >> 5;
    const int lane = tid & 31;
    const int wm = wid >> 2;
    const int wn = wid & 3;
    const int bm = blockIdx.y * 128;
    const int bn = blockIdx.x * 128;
    const int z = blockIdx.z;
    const int mode = (base_mode == 0) ? 0 : 1 + z;
    const float* bias = (z == 0) ? bias0 : (z == 1) ? bias1 : bias2;

    const int aslot = (mode == 0) ? 0 : mode - 1;
    const int wslot = (mode == 0) ? 3 : mode - 1;
    const __nv_bfloat16* Ahi = g_Ahi + (size_t)aslot * NM * ND;
    const __nv_bfloat16* Alo = g_Alo + (size_t)aslot * NM * ND;
    const __nv_bfloat16* Whi = g_Whi + (size_t)wslot * ND * ND;
    const __nv_bfloat16* Wlo = g_Wlo + (size_t)wslot * ND * ND;

    const __nv_bfloat16* srcs[4] = {Ahi, Alo, Whi, Wlo};
    const int row0[4] = {bm, bm, bn, bn};
    const uint32_t toff[4] = {GOFF_AHI, GOFF_ALO, GOFF_WHI, GOFF_WLO};

    float acc[2][4][4];
#pragma unroll
    for (int mi = 0; mi < 2; mi++)
#pragma unroll
        for (int c = 0; c < 4; c++)
#pragma unroll
            for (int t = 0; t < 4; t++) acc[mi][c][t] = 0.f;

    const uint32_t aRow = (uint32_t)(wm * 32 + (lane & 15));
    const uint32_t aKb  = (uint32_t)((lane >> 4) << 4);
    const uint32_t bRow = (uint32_t)(wn * 32 + (lane & 7) + ((lane >> 4) & 1) * 8);
    const uint32_t bKb  = (uint32_t)(((lane >> 3) & 1) << 4);

    auto load_stage = [&](int kc) {
        const int k0 = kc * 64;
        const uint32_t sbase = sb + (uint32_t)((kc % 3) * GSTAGE);
#pragma unroll
        for (int t = 0; t < 4; t++) {
#pragma unroll
            for (int u = 0; u < 2; u++) {
                int idx = u * 512 + tid;
                int r = idx >> 3, c = idx & 7;
                uint32_t bo = (uint32_t)(r * 128 + c * 16);
                cp_async16(sbase + toff[t] + SW128(bo),
                           srcs[t] + (size_t)(row0[t] + r) * ND + k0 + c * 8);
            }
        }
    };

    load_stage(0); CP_COMMIT();
    load_stage(1); CP_COMMIT();

    for (int kc = 0; kc < 16; kc++) {
        if (kc < 14) CP_WAIT1(); else CP_WAIT0();
        __syncthreads();                   // publishes stage kc; frees buf (kc+2)%3
        if (kc < 14) { load_stage(kc + 2); CP_COMMIT(); }

        const uint32_t stage = sb + (uint32_t)((kc % 3) * GSTAGE);
#pragma unroll
        for (int ks = 0; ks < 4; ks++) {
            uint32_t ah[2][4], al[2][4];
#pragma unroll
            for (int mi = 0; mi < 2; mi++) {
                uint32_t off = SW128((aRow + mi * 16) * 128 + (uint32_t)(ks * 32) + aKb);
                ldm_x4(ah[mi][0], ah[mi][1], ah[mi][2], ah[mi][3], stage + GOFF_AHI + off);
                ldm_x4(al[mi][0], al[mi][1], al[mi][2], al[mi][3], stage + GOFF_ALO + off);
            }
            uint32_t bh[2][4], bl[2][4];
#pragma unroll
            for (int nj = 0; nj < 2; nj++) {
                uint32_t off = SW128((bRow + nj * 16) * 128 + (uint32_t)(ks * 32) + bKb);
                ldm_x4(bh[nj][0], bh[nj][1], bh[nj][2], bh[nj][3], stage + GOFF_WHI + off);
                ldm_x4(bl[nj][0], bl[nj][1], bl[nj][2], bl[nj][3], stage + GOFF_WLO + off);
            }
#pragma unroll
            for (int mi = 0; mi < 2; mi++)
#pragma unroll
                for (int nj = 0; nj < 2; nj++) {
                    mma16816(acc[mi][nj * 2 + 0], ah[mi], &bh[nj][0]);
                    mma16816(acc[mi][nj * 2 + 1], ah[mi], &bh[nj][2]);
                }
#pragma unroll
            for (int mi = 0; mi < 2; mi++)
#pragma unroll
                for (int nj = 0; nj < 2; nj++) {
                    mma16816(acc[mi][nj * 2 + 0], al[mi], &bh[nj][0]);
                    mma16816(acc[mi][nj * 2 + 1], al[mi], &bh[nj][2]);
                }
#pragma unroll
            for (int mi = 0; mi < 2; mi++)
#pragma unroll
                for (int nj = 0; nj < 2; nj++) {
                    mma16816(acc[mi][nj * 2 + 0], ah[mi], &bl[nj][0]);
                    mma16816(acc[mi][nj * 2 + 1], ah[mi], &bl[nj][2]);
                }
        }
    }

    // Epilogue
    __nv_bfloat16 *dHi = nullptr, *dLo = nullptr;
    if (mode == 1) { dHi = g_Qhi; dLo = g_Qlo; }
    else if (mode == 2) { dHi = g_Khi; dLo = g_Klo; }
    else if (mode == 3) { dHi = g_Vhi; dLo = g_Vlo; }

    const int g = lane >> 2, tg = lane & 3;
#pragma unroll
    for (int mi = 0; mi < 2; mi++) {
#pragma unroll
        for (int c = 0; c < 4; c++) {
            int n = bn + wn * 32 + c * 8 + tg * 2;
            float bx = bias[n], by = bias[n + 1];
            int m0 = bm + wm * 32 + mi * 16 + g;
#pragma unroll
            for (int half = 0; half < 2; half++) {
                int m = m0 + half * 8;
                float ox = acc[mi][c][half * 2 + 0] + bx;
                float oy = acc[mi][c][half * 2 + 1] + by;
                if (mode == 0) {
                    *(float2*)(Cp + (size_t)m * ND + n) = make_float2(ox, oy);
                } else {
                    int bb = m >> 11, ss = m & 2047;
                    int h = n >> 6, dd = n & 63;
                    size_t idx = (((size_t)(bb * NH + h) * NS + ss) * NDK) + dd;
                    uint32_t hi, lo;
                    split_pair(ox, oy, hi, lo);
                    *(uint32_t*)(dHi + idx) = hi;
                    *(uint32_t*)(dLo + idx) = lo;
                }
            }
        }
    }
}

// ---------------------------------------------------------------------------
// PERSISTENT flash attention, KV-split at 2 CTAs/SM.
// 296 CTAs x 256 threads; warp grid 4(m) x 2(kv); q-tile 64 rows.
// Per-SM smem traffic/KV-tile: 2560 read + 1024 write cyc vs 2702 tensor
// (R13 was 4608 + 512). Barrier drain overlapped by the co-resident CTA.
// Cross-kv-half reduction once per tile via (idle) KV stage smem.
// Smem: Qhi/Qlo 16KB + 2 stages x 32KB = 80KB -> 2 CTAs/SM.
// ---------------------------------------------------------------------------
#define FQHI 0
#define FQLO 8192
#define FSTG 16384
#define FKHI 0
#define FKLO 8192
#define FVHI 16384
#define FVLO 24576
#define FLASH_SMEM (16384 + 2 * 32768)   // 81920
#define N_TILES (NB * NH * (NS / 64))    // 2048

#define EXP_K2 0.18033688011112042f     // 0.125 * log2(e)
#define EXP_C2 23.083120654223414f      // 16 * log2(e)

__global__ __launch_bounds__(256, 2) void flash_mma(void)
{
    extern __shared__ __align__(1024) char fsm[];
    __shared__ int s_tile;
    const uint32_t sb = smem_u32(fsm);
    const int tid = threadIdx.x;
    const int wid = tid >> 5;
    const int lane = tid & 31;
    const int g = lane >> 2, tg = lane & 3;
    const int wm = wid & 3;      // m16 row group (0..3) -> 64 q rows
    const int wg = wid >> 2;     // kv half (0..1)

    // fragment address components
    const uint32_t aRow = (uint32_t)(wm * 16 + (lane & 15));
    const uint32_t aKb  = (uint32_t)((lane >> 4) << 4);
    const uint32_t bRow = (uint32_t)(wg * 32 + (lane & 7) + ((lane >> 4) & 1) * 8);
    const uint32_t bKb  = (uint32_t)(((lane >> 3) & 1) << 4);
    const uint32_t vRow = (uint32_t)(wg * 32 + (lane & 7) + ((lane >> 3) & 1) * 8); // trans
    const uint32_t vNb  = (uint32_t)(((lane >> 4) & 1) << 4);

    for (;;) {
        __syncthreads();   // prior tile fully consumed (smem + redbuf safe)
        if (tid == 0) s_tile = atomicAdd(&g_tile_counter, 1);
        __syncthreads();
        const int t = s_tile;
        if (t >= N_TILES) break;

        const int qt = t & 31;            // 32 q-tiles of 64 rows
        const int h  = (t >> 5) & 15;
        const int b  = t >> 9;

        const size_t kvbase = (size_t)(b * NH + h) * NS * NDK;
        const size_t qbase  = kvbase + (size_t)qt * 64 * NDK;

        // Q tile (64 rows) + first KV stage
#pragma unroll
        for (int u = 0; u < 2; u++) {
            int idx = u * 256 + tid;
            int r = idx >> 3, c = idx & 7;
            uint32_t bo = SW128((uint32_t)(r * 128 + c * 16));
            size_t go = qbase + (size_t)r * NDK + c * 8;
            cp_async16(sb + FQHI + bo, g_Qhi + go);
            cp_async16(sb + FQLO + bo, g_Qlo + go);
        }
#pragma unroll
        for (int u = 0; u < 2; u++) {
            int idx = u * 256 + tid;
            int r = idx >> 3, c = idx & 7;
            uint32_t bo = SW128((uint32_t)(r * 128 + c * 16));
            size_t go = kvbase + (size_t)r * NDK + c * 8;
            cp_async16(sb + FSTG + FKHI + bo, g_Khi + go);
            cp_async16(sb + FSTG + FKLO + bo, g_Klo + go);
            cp_async16(sb + FSTG + FVHI + bo, g_Vhi + go);
            cp_async16(sb + FSTG + FVLO + bo, g_Vlo + go);
        }
        CP_COMMIT();

        float o[8][4];                     // m16 x d64 partial (kv half)
#pragma unroll
        for (int nj = 0; nj < 8; nj++)
#pragma unroll
            for (int tt = 0; tt < 4; tt++) o[nj][tt] = 0.f;
        float lsum0 = 0.f, lsum1 = 0.f;    // partial row sums (kv half)
        const int qg0 = qt * 64 + wm * 16 + g;

        for (int kt = 0; kt < NS / 64; kt++) {
            CP_WAIT0();
            __syncthreads();             // publishes stage kt; frees buf (kt+1)&1
            if (kt < NS / 64 - 1) {
                uint32_t sbase = sb + FSTG + (uint32_t)(((kt + 1) & 1) * 32768);
#pragma unroll
                for (int u = 0; u < 2; u++) {
                    int idx = u * 256 + tid;
                    int r = idx >> 3, c = idx & 7;
                    uint32_t bo = SW128((uint32_t)(r * 128 + c * 16));
                    size_t go = kvbase + (size_t)((kt + 1) * 64 + r) * NDK + c * 8;
                    cp_async16(sbase + FKHI + bo, g_Khi + go);
                    cp_async16(sbase + FKLO + bo, g_Klo + go);
                    cp_async16(sbase + FVHI + bo, g_Vhi + go);
                    cp_async16(sbase + FVLO + bo, g_Vlo + go);
                }
                CP_COMMIT();
            }

            const uint32_t st = sb + FSTG + (uint32_t)((kt & 1) * 32768);

            // QK^T: sc[nj 0..3][4] for this warp's kv32 half
            float sc[4][4];
#pragma unroll
            for (int nj = 0; nj < 4; nj++)
#pragma unroll
                for (int tt = 0; tt < 4; tt++) sc[nj][tt] = 0.f;

#pragma unroll
            for (int kk = 0; kk < 4; kk++) {
                uint32_t qh4[4], ql4[4];
                uint32_t qo = SW128(aRow * 128 + (uint32_t)(kk * 32) + aKb);
                ldm_x4(qh4[0], qh4[1], qh4[2], qh4[3], sb + FQHI + qo);
                ldm_x4(ql4[0], ql4[1], ql4[2], ql4[3], sb + FQLO + qo);
#pragma unroll
                for (int njl = 0; njl < 2; njl++) {
                    uint32_t bo = SW128((bRow + njl * 16) * 128 + (uint32_t)(kk * 32) + bKb);
                    uint32_t bh4[4], bl4[4];
                    ldm_x4(bh4[0], bh4[1], bh4[2], bh4[3], st + FKHI + bo);
                    ldm_x4(bl4[0], bl4[1], bl4[2], bl4[3], st + FKLO + bo);
                    mma16816(sc[2 * njl + 0], qh4, &bh4[0]);
                    mma16816(sc[2 * njl + 1], qh4, &bh4[2]);
                    mma16816(sc[2 * njl + 0], ql4, &bh4[0]);
                    mma16816(sc[2 * njl + 1], ql4, &bh4[2]);
                    mma16816(sc[2 * njl + 0], qh4, &bl4[0]);
                    mma16816(sc[2 * njl + 1], qh4, &bl4[2]);
                }
            }

            // mask (bitmap, this warp's 32-bit half) + fixed-max exp2 softmax
            uint2 w0 = *(const uint2*)(g_maskbits + (size_t)qg0 * 32 + kt);
            uint2 w1 = *(const uint2*)(g_maskbits + (size_t)(qg0 + 8) * 32 + kt);
            unsigned m0w = wg ? w0.y : w0.x;
            unsigned m1w = wg ? w1.y : w1.x;
            float rs0 = 0.f, rs1 = 0.f;
#pragma unroll
            for (int nj = 0; nj < 4; nj++) {
                int sh = nj * 8 + tg * 2;
                unsigned b0 = m0w >> sh, b1 = m1w >> sh;
                float p0 = ex2f((b0 & 1) ? fmaf(sc[nj][0], EXP_K2, -EXP_C2) : -1e9f);
                float p1 = ex2f((b0 & 2) ? fmaf(sc[nj][1], EXP_K2, -EXP_C2) : -1e9f);
                float p2 = ex2f((b1 & 1) ? fmaf(sc[nj][2], EXP_K2, -EXP_C2) : -1e9f);
                float p3 = ex2f((b1 & 2) ? fmaf(sc[nj][3], EXP_K2, -EXP_C2) : -1e9f);
                sc[nj][0] = p0; sc[nj][1] = p1;
                sc[nj][2] = p2; sc[nj][3] = p3;
                rs0 += p0 + p1;
                rs1 += p2 + p3;
            }
            rs0 += __shfl_xor_sync(0xffffffffu, rs0, 1);
            rs0 += __shfl_xor_sync(0xffffffffu, rs0, 2);
            rs1 += __shfl_xor_sync(0xffffffffu, rs1, 1);
            rs1 += __shfl_xor_sync(0xffffffffu, rs1, 2);
            lsum0 += rs0;
            lsum1 += rs1;

            // P*V over this warp's kv32 (2 kv16 steps)
#pragma unroll
            for (int kk2 = 0; kk2 < 2; kk2++) {
                uint32_t ph[4], pl[4];
                split_pair(sc[2 * kk2][0],     sc[2 * kk2][1],     ph[0], pl[0]);
                split_pair(sc[2 * kk2][2],     sc[2 * kk2][3],     ph[1], pl[1]);
                split_pair(sc[2 * kk2 + 1][0], sc[2 * kk2 + 1][1], ph[2], pl[2]);
                split_pair(sc[2 * kk2 + 1][2], sc[2 * kk2 + 1][3], ph[3], pl[3]);
#pragma unroll
                for (int njp = 0; njp < 4; njp++) {
                    uint32_t bo = SW128((uint32_t)(kk2 * 16 + vRow) * 128 +
                                        (uint32_t)(njp * 32) + vNb);
                    uint32_t vh4[4], vl4[4];
                    ldm_x4t(vh4[0], vh4[1], vh4[2], vh4[3], st + FVHI + bo);
                    ldm_x4t(vl4[0], vl4[1], vl4[2], vl4[3], st + FVLO + bo);
                    mma16816(o[2 * njp + 0], ph, &vh4[0]);
                    mma16816(o[2 * njp + 1], ph, &vh4[2]);
                    mma16816(o[2 * njp + 0], pl, &vh4[0]);
                    mma16816(o[2 * njp + 1], pl, &vh4[2]);
                    mma16816(o[2 * njp + 0], ph, &vl4[0]);
                    mma16816(o[2 * njp + 1], ph, &vl4[2]);
                }
            }
        }

        // Epilogue: cross-warp (kv half) reduction via smem, then write output.
        __syncthreads();   // all reads of KV stage smem done -> safe to reuse
        float* redbuf = (float*)(fsm + FSTG);            // 64 x 64 fp32 = 16KB
        float* lsbuf  = (float*)(fsm + FSTG + 16384);    // 64 fp32
        const int rl0 = wm * 16 + g;
        if (wg == 0) {
#pragma unroll
            for (int nj = 0; nj < 8; nj++) {
                int col = nj * 8 + tg * 2;
                *(float2*)&redbuf[(rl0)     * 64 + col] = make_float2(o[nj][0], o[nj][1]);
                *(float2*)&redbuf[(rl0 + 8) * 64 + col] = make_float2(o[nj][2], o[nj][3]);
            }
            if (tg == 0) { lsbuf[rl0] = lsum0; lsbuf[rl0 + 8] = lsum1; }
        }
        __syncthreads();
        if (wg == 1) {
            float inv0 = 1.f / (lsum0 + lsbuf[rl0]);
            float inv1 = 1.f / (lsum1 + lsbuf[rl0 + 8]);
            const size_t row0 = (size_t)(b * NS + qg0) * ND;
            const size_t row1 = row0 + (size_t)8 * ND;
#pragma unroll
            for (int nj = 0; nj < 8; nj++) {
                int col = nj * 8 + tg * 2;
                float2 p0 = *(float2*)&redbuf[(rl0)     * 64 + col];
                float2 p1 = *(float2*)&redbuf[(rl0 + 8) * 64 + col];
                int gcol = h * NDK + col;
                uint32_t hi, lo;
                split_pair((o[nj][0] + p0.x) * inv0, (o[nj][1] + p0.y) * inv0, hi, lo);
                *(uint32_t*)(g_Ahi + row0 + gcol) = hi;
                *(uint32_t*)(g_Alo + row0 + gcol) = lo;
                split_pair((o[nj][2] + p1.x) * inv1, (o[nj][3] + p1.y) * inv1, hi, lo);
                *(uint32_t*)(g_Ahi + row1 + gcol) = hi;
                *(uint32_t*)(g_Alo + row1 + gcol) = lo;
            }
        }
    }
}

// ---------------------------------------------------------------------------
extern "C" void kernel_launch(void* const* d_in, const int* in_sizes, int n_in,
                              void* d_out, int out_size)
{
    const float* q    = (const float*)d_in[0];
    const float* k    = (const float*)d_in[1];
    const float* v    = (const float*)d_in[2];
    const int*   mask = (const int*)d_in[3];
    const float* w_q  = (const float*)d_in[4];
    const float* b_q  = (const float*)d_in[5];
    const float* w_k  = (const float*)d_in[6];
    const float* b_k  = (const float*)d_in[7];
    const float* w_v  = (const float*)d_in[8];
    const float* b_v  = (const float*)d_in[9];
    const float* w_o  = (const float*)d_in[10];
    const float* b_o  = (const float*)d_in[11];

    cudaFuncSetAttribute(gemm_tc, cudaFuncAttributeMaxDynamicSharedMemorySize, GEMM_SMEM);
    cudaFuncSetAttribute(flash_mma, cudaFuncAttributeMaxDynamicSharedMemorySize, FLASH_SMEM);

    const int actBlocks = NM * ND / (4 * 256);  // 8192
    const int wBlocks   = ND * ND / (4 * 256);  // 1024

    mask_pack<<<NS * NS / 64 / 256, 256>>>(mask);   // also resets tile counter

    dim3 agrid_s(actBlocks, 3);
    split_act<<<agrid_s, 256>>>(q, k, v);
    dim3 wgrid(wBlocks, 4);
    split_wgt<<<wgrid, 256>>>(w_q, w_k, w_v, w_o);

    dim3 qkvgrid(ND / 128, NM / 128, 3);        // (8, 64, 3)
    gemm_tc<<<qkvgrid, 512, GEMM_SMEM>>>(b_q, b_k, b_v, nullptr, 1);

    flash_mma<<<296, 256, FLASH_SMEM>>>();      // persistent: 2 CTAs/SM

    dim3 ogrid(ND / 128, NM / 128, 1);          // (8, 64)
    gemm_tc<<<ogrid, 512, GEMM_SMEM>>>(b_o, b_o, b_o, (float*)d_out, 0);
}

// round 16
// speedup vs baseline: 1.0824x; 1.0409x over previous
#include <cuda_runtime.h>
#include <cuda_bf16.h>
#include <cstdint>

typedef unsigned long long u64;

// Problem constants
#define NB 4
#define NS 2048
#define ND 1024
#define NH 16
#define NDK 64
#define NM (NB * NS)   // 8192 rows

// ---------------------------------------------------------------------------
// Scratch (device globals: allocation-free)
// ---------------------------------------------------------------------------
__device__ __align__(16) __nv_bfloat16 g_Ahi[3 * NM * ND];
__device__ __align__(16) __nv_bfloat16 g_Alo[3 * NM * ND];
__device__ __align__(16) __nv_bfloat16 g_Whi[4 * ND * ND];
__device__ __align__(16) __nv_bfloat16 g_Wlo[4 * ND * ND];
__device__ __align__(16) __nv_bfloat16 g_Qhi[NB * NH * NS * NDK];  // [B,H,S,dk]
__device__ __align__(16) __nv_bfloat16 g_Qlo[NB * NH * NS * NDK];
__device__ __align__(16) __nv_bfloat16 g_Khi[NB * NH * NS * NDK];
__device__ __align__(16) __nv_bfloat16 g_Klo[NB * NH * NS * NDK];
__device__ __align__(16) __nv_bfloat16 g_Vhi[NB * NH * NS * NDK];
__device__ __align__(16) __nv_bfloat16 g_Vlo[NB * NH * NS * NDK];
__device__ __align__(16) u64 g_maskbits[NS * NS / 64];    // bit-packed mask
__device__ int g_tile_counter;                            // persistent-flash work queue

// ---------------------------------------------------------------------------
// Helpers
// ---------------------------------------------------------------------------
__device__ __forceinline__ uint32_t smem_u32(const void* p) {
    uint32_t a;
    asm("{ .reg .u64 t; cvta.to.shared.u64 t, %1; cvt.u32.u64 %0, t; }" : "=r"(a) : "l"(p));
    return a;
}
#define SW128(bo) ((bo) ^ (((bo) >> 3) & 0x70))

__device__ __forceinline__ void ldm_x4(uint32_t& r0, uint32_t& r1, uint32_t& r2,
                                       uint32_t& r3, uint32_t addr) {
    asm volatile("ldmatrix.sync.aligned.m8n8.x4.shared.b16 {%0,%1,%2,%3}, [%4];"
                 : "=r"(r0), "=r"(r1), "=r"(r2), "=r"(r3) : "r"(addr));
}
__device__ __forceinline__ void ldm_x4t(uint32_t& r0, uint32_t& r1, uint32_t& r2,
                                        uint32_t& r3, uint32_t addr) {
    asm volatile("ldmatrix.sync.aligned.m8n8.x4.trans.shared.b16 {%0,%1,%2,%3}, [%4];"
                 : "=r"(r0), "=r"(r1), "=r"(r2), "=r"(r3) : "r"(addr));
}
__device__ __forceinline__ void mma16816(float* d, const uint32_t* a, const uint32_t* b) {
    asm volatile("mma.sync.aligned.m16n8k16.row.col.f32.bf16.bf16.f32 "
                 "{%0,%1,%2,%3}, {%4,%5,%6,%7}, {%8,%9}, {%0,%1,%2,%3};"
                 : "+f"(d[0]), "+f"(d[1]), "+f"(d[2]), "+f"(d[3])
                 : "r"(a[0]), "r"(a[1]), "r"(a[2]), "r"(a[3]), "r"(b[0]), "r"(b[1]));
}

__device__ __forceinline__ void cp_async16(uint32_t s, const void* g) {
    asm volatile("{ .reg .u64 gg; cvta.to.global.u64 gg, %1; "
                 "cp.async.cg.shared.global [%0], [gg], 16; }"
                 :: "r"(s), "l"(g) : "memory");
}
#define CP_COMMIT() asm volatile("cp.async.commit_group;" ::: "memory")
#define CP_WAIT1()  asm volatile("cp.async.wait_group 1;" ::: "memory")
#define CP_WAIT0()  asm volatile("cp.async.wait_group 0;" ::: "memory")

__device__ __forceinline__ float ex2f(float x) {
    float r;
    asm("ex2.approx.f32 %0, %1;" : "=f"(r) : "f"(x));
    return r;
}

// split fp32 pair -> packed bf16 hi pair + bf16 residual pair
__device__ __forceinline__ void split_pair(float a, float b, uint32_t& hi, uint32_t& lo) {
    __nv_bfloat16 ha = __float2bfloat16(a), hb = __float2bfloat16(b);
    __nv_bfloat16 la = __float2bfloat16(a - __bfloat162float(ha));
    __nv_bfloat16 lb = __float2bfloat16(b - __bfloat162float(hb));
    __nv_bfloat162 H(ha, hb), L(la, lb);
    hi = *reinterpret_cast<uint32_t*>(&H);
    lo = *reinterpret_cast<uint32_t*>(&L);
}

// split 8 contiguous fp32 -> 16B hi plane + 16B lo plane
__device__ __forceinline__ void split8(const float* __restrict__ src,
                                       __nv_bfloat16* dhi, __nv_bfloat16* dlo, size_t i)
{
    float4 v0 = *(const float4*)(src + i);
    float4 v1 = *(const float4*)(src + i + 4);
    uint4 H, L;
    split_pair(v0.x, v0.y, H.x, L.x);
    split_pair(v0.z, v0.w, H.y, L.y);
    split_pair(v1.x, v1.y, H.z, L.z);
    split_pair(v1.z, v1.w, H.w, L.w);
    *(uint4*)(dhi + i) = H;
    *(uint4*)(dlo + i) = L;
}

// ---------------------------------------------------------------------------
// Fused preprocess: ONE launch.
// blocks [0,256):        mask_pack (+ tile counter reset)
// blocks [256,12544):    split_act (3 slots x 4096 blocks, 8 elems/thread)
// blocks [12544,14592):  split_wgt (4 slots x 512 blocks, 8 elems/thread)
// ---------------------------------------------------------------------------
#define PREP_BLOCKS (256 + 3 * 4096 + 4 * 512)   // 14592

__global__ __launch_bounds__(256) void prep(
    const int* __restrict__ mask,
    const float* __restrict__ a0, const float* __restrict__ a1,
    const float* __restrict__ a2,
    const float* __restrict__ w0, const float* __restrict__ w1,
    const float* __restrict__ w2, const float* __restrict__ w3)
{
    const int bid = blockIdx.x;
    const int tid = threadIdx.x;
    if (bid < 256) {
        if (bid == 0 && tid == 0) g_tile_counter = 0;
        int w = bid * 256 + tid;     // 0 .. 65535
        const int4* src = (const int4*)(mask + (size_t)w * 64);
        u64 bits = 0;
#pragma unroll
        for (int q = 0; q < 16; q++) {
            int4 v = src[q];
            bits |= ((u64)(v.x != 0) << (q * 4 + 0)) | ((u64)(v.y != 0) << (q * 4 + 1))
                  | ((u64)(v.z != 0) << (q * 4 + 2)) | ((u64)(v.w != 0) << (q * 4 + 3));
        }
        g_maskbits[w] = bits;
    } else if (bid < 12544) {
        int rel = bid - 256;
        int slot = rel >> 12;                    // /4096
        const float* src = (slot == 0) ? a0 : (slot == 1) ? a1 : a2;
        size_t base = (size_t)slot * NM * ND;
        size_t i = ((size_t)(rel & 4095) * 256 + tid) * 8;
        split8(src, g_Ahi + base, g_Alo + base, i);
    } else {
        int rel = bid - 12544;
        int slot = rel >> 9;                     // /512
        const float* src = (slot == 0) ? w0 : (slot == 1) ? w1 : (slot == 2) ? w2 : w3;
        size_t base = (size_t)slot * ND * ND;
        size_t i = ((size_t)(rel & 511) * 256 + tid) * 8;
        split8(src, g_Whi + base, g_Wlo + base, i);
    }
}

// ---------------------------------------------------------------------------
// mma.sync GEMM, 3-stage cp.async pipeline, ONE barrier per K-chunk.
// 512 threads / 16 warps; warp grid 4(m) x 4(n): warp tile 32x32. (proven)
// ---------------------------------------------------------------------------
#define GOFF_AHI 0
#define GOFF_ALO 16384
#define GOFF_WHI 32768
#define GOFF_WLO 49152
#define GSTAGE   65536
#define GEMM_SMEM (3 * GSTAGE)   // 196608

__global__ __launch_bounds__(512) void gemm_tc(
    const float* __restrict__ bias0, const float* __restrict__ bias1,
    const float* __restrict__ bias2, float* __restrict__ Cp, int base_mode)
{
    extern __shared__ __align__(1024) char smem[];
    const uint32_t sb = smem_u32(smem);
    const int tid = threadIdx.x;
    const int wid = tid >> 5;
    const int lane = tid & 31;
    const int wm = wid >> 2;
    const int wn = wid & 3;
    const int bm = blockIdx.y * 128;
    const int bn = blockIdx.x * 128;
    const int z = blockIdx.z;
    const int mode = (base_mode == 0) ? 0 : 1 + z;
    const float* bias = (z == 0) ? bias0 : (z == 1) ? bias1 : bias2;

    const int aslot = (mode == 0) ? 0 : mode - 1;
    const int wslot = (mode == 0) ? 3 : mode - 1;
    const __nv_bfloat16* Ahi = g_Ahi + (size_t)aslot * NM * ND;
    const __nv_bfloat16* Alo = g_Alo + (size_t)aslot * NM * ND;
    const __nv_bfloat16* Whi = g_Whi + (size_t)wslot * ND * ND;
    const __nv_bfloat16* Wlo = g_Wlo + (size_t)wslot * ND * ND;

    const __nv_bfloat16* srcs[4] = {Ahi, Alo, Whi, Wlo};
    const int row0[4] = {bm, bm, bn, bn};
    const uint32_t toff[4] = {GOFF_AHI, GOFF_ALO, GOFF_WHI, GOFF_WLO};

    float acc[2][4][4];
#pragma unroll
    for (int mi = 0; mi < 2; mi++)
#pragma unroll
        for (int c = 0; c < 4; c++)
#pragma unroll
            for (int t = 0; t < 4; t++) acc[mi][c][t] = 0.f;

    const uint32_t aRow = (uint32_t)(wm * 32 + (lane & 15));
    const uint32_t aKb  = (uint32_t)((lane >> 4) << 4);
    const uint32_t bRow = (uint32_t)(wn * 32 + (lane & 7) + ((lane >> 4) & 1) * 8);
    const uint32_t bKb  = (uint32_t)(((lane >> 3) & 1) << 4);

    auto load_stage = [&](int kc) {
        const int k0 = kc * 64;
        const uint32_t sbase = sb + (uint32_t)((kc % 3) * GSTAGE);
#pragma unroll
        for (int t = 0; t < 4; t++) {
#pragma unroll
            for (int u = 0; u < 2; u++) {
                int idx = u * 512 + tid;
                int r = idx >> 3, c = idx & 7;
                uint32_t bo = (uint32_t)(r * 128 + c * 16);
                cp_async16(sbase + toff[t] + SW128(bo),
                           srcs[t] + (size_t)(row0[t] + r) * ND + k0 + c * 8);
            }
        }
    };

    load_stage(0); CP_COMMIT();
    load_stage(1); CP_COMMIT();

    for (int kc = 0; kc < 16; kc++) {
        if (kc < 14) CP_WAIT1(); else CP_WAIT0();
        __syncthreads();                   // publishes stage kc; frees buf (kc+2)%3
        if (kc < 14) { load_stage(kc + 2); CP_COMMIT(); }

        const uint32_t stage = sb + (uint32_t)((kc % 3) * GSTAGE);
#pragma unroll
        for (int ks = 0; ks < 4; ks++) {
            uint32_t ah[2][4], al[2][4];
#pragma unroll
            for (int mi = 0; mi < 2; mi++) {
                uint32_t off = SW128((aRow + mi * 16) * 128 + (uint32_t)(ks * 32) + aKb);
                ldm_x4(ah[mi][0], ah[mi][1], ah[mi][2], ah[mi][3], stage + GOFF_AHI + off);
                ldm_x4(al[mi][0], al[mi][1], al[mi][2], al[mi][3], stage + GOFF_ALO + off);
            }
            uint32_t bh[2][4], bl[2][4];
#pragma unroll
            for (int nj = 0; nj < 2; nj++) {
                uint32_t off = SW128((bRow + nj * 16) * 128 + (uint32_t)(ks * 32) + bKb);
                ldm_x4(bh[nj][0], bh[nj][1], bh[nj][2], bh[nj][3], stage + GOFF_WHI + off);
                ldm_x4(bl[nj][0], bl[nj][1], bl[nj][2], bl[nj][3], stage + GOFF_WLO + off);
            }
#pragma unroll
            for (int mi = 0; mi < 2; mi++)
#pragma unroll
                for (int nj = 0; nj < 2; nj++) {
                    mma16816(acc[mi][nj * 2 + 0], ah[mi], &bh[nj][0]);
                    mma16816(acc[mi][nj * 2 + 1], ah[mi], &bh[nj][2]);
                }
#pragma unroll
            for (int mi = 0; mi < 2; mi++)
#pragma unroll
                for (int nj = 0; nj < 2; nj++) {
                    mma16816(acc[mi][nj * 2 + 0], al[mi], &bh[nj][0]);
                    mma16816(acc[mi][nj * 2 + 1], al[mi], &bh[nj][2]);
                }
#pragma unroll
            for (int mi = 0; mi < 2; mi++)
#pragma unroll
                for (int nj = 0; nj < 2; nj++) {
                    mma16816(acc[mi][nj * 2 + 0], ah[mi], &bl[nj][0]);
                    mma16816(acc[mi][nj * 2 + 1], ah[mi], &bl[nj][2]);
                }
        }
    }

    // Epilogue
    __nv_bfloat16 *dHi = nullptr, *dLo = nullptr;
    if (mode == 1) { dHi = g_Qhi; dLo = g_Qlo; }
    else if (mode == 2) { dHi = g_Khi; dLo = g_Klo; }
    else if (mode == 3) { dHi = g_Vhi; dLo = g_Vlo; }

    const int g = lane >> 2, tg = lane & 3;
#pragma unroll
    for (int mi = 0; mi < 2; mi++) {
#pragma unroll
        for (int c = 0; c < 4; c++) {
            int n = bn + wn * 32 + c * 8 + tg * 2;
            float bx = bias[n], by = bias[n + 1];
            int m0 = bm + wm * 32 + mi * 16 + g;
#pragma unroll
            for (int half = 0; half < 2; half++) {
                int m = m0 + half * 8;
                float ox = acc[mi][c][half * 2 + 0] + bx;
                float oy = acc[mi][c][half * 2 + 1] + by;
                if (mode == 0) {
                    *(float2*)(Cp + (size_t)m * ND + n) = make_float2(ox, oy);
                } else {
                    int bb = m >> 11, ss = m & 2047;
                    int h = n >> 6, dd = n & 63;
                    size_t idx = (((size_t)(bb * NH + h) * NS + ss) * NDK) + dd;
                    uint32_t hi, lo;
                    split_pair(ox, oy, hi, lo);
                    *(uint32_t*)(dHi + idx) = hi;
                    *(uint32_t*)(dLo + idx) = lo;
                }
            }
        }
    }
}

// ---------------------------------------------------------------------------
// PERSISTENT flash attention on tensor cores (split bf16, 3-MMA).
// 296 CTAs (2/SM), 256 threads; fixed-max exp2 softmax. (R13 best: 1081.8us)
// ---------------------------------------------------------------------------
#define FQHI 0
#define FQLO 16384
#define FSTG 32768
#define FKHI 0
#define FKLO 8192
#define FVHI 16384
#define FVLO 24576
#define FLASH_SMEM (32768 + 2 * 32768)   // 98304
#define N_TILES (NB * NH * (NS / 128))   // 1024

#define EXP_K2 0.18033688011112042f     // 0.125 * log2(e)
#define EXP_C2 23.083120654223414f      // 16 * log2(e)

__global__ __launch_bounds__(256, 2) void flash_mma(void)
{
    extern __shared__ __align__(1024) char fsm[];
    __shared__ int s_tile;
    const uint32_t sb = smem_u32(fsm);
    const int tid = threadIdx.x;
    const int wid = tid >> 5;
    const int lane = tid & 31;
    const int g = lane >> 2, tg = lane & 3;

    // fragment address components (tile-independent)
    const uint32_t aRow = (uint32_t)(wid * 16 + (lane & 15));
    const uint32_t aKb  = (uint32_t)((lane >> 4) << 4);
    const uint32_t bRow = (uint32_t)((lane & 7) + ((lane >> 4) & 1) * 8);
    const uint32_t bKb  = (uint32_t)(((lane >> 3) & 1) << 4);
    const uint32_t vRow = (uint32_t)((lane & 7) + ((lane >> 3) & 1) * 8);   // trans
    const uint32_t vNb  = (uint32_t)(((lane >> 4) & 1) << 4);

    for (;;) {
        __syncthreads();   // prior tile fully consumed (smem safe) + s_tile reuse
        if (tid == 0) s_tile = atomicAdd(&g_tile_counter, 1);
        __syncthreads();
        const int t = s_tile;
        if (t >= N_TILES) break;

        const int qt = t & 15;
        const int h  = (t >> 4) & 15;
        const int b  = t >> 8;

        const size_t kvbase = (size_t)(b * NH + h) * NS * NDK;
        const size_t qbase  = kvbase + (size_t)qt * 128 * NDK;

        // Q tile + first KV stage
#pragma unroll
        for (int u = 0; u < 4; u++) {
            int idx = u * 256 + tid;
            int r = idx >> 3, c = idx & 7;
            uint32_t bo = SW128((uint32_t)(r * 128 + c * 16));
            size_t go = qbase + (size_t)r * NDK + c * 8;
            cp_async16(sb + FQHI + bo, g_Qhi + go);
            cp_async16(sb + FQLO + bo, g_Qlo + go);
        }
#pragma unroll
        for (int u = 0; u < 2; u++) {
            int idx = u * 256 + tid;
            int r = idx >> 3, c = idx & 7;
            uint32_t bo = SW128((uint32_t)(r * 128 + c * 16));
            size_t go = kvbase + (size_t)r * NDK + c * 8;
            cp_async16(sb + FSTG + FKHI + bo, g_Khi + go);
            cp_async16(sb + FSTG + FKLO + bo, g_Klo + go);
            cp_async16(sb + FSTG + FVHI + bo, g_Vhi + go);
            cp_async16(sb + FSTG + FVLO + bo, g_Vlo + go);
        }
        CP_COMMIT();

        float o[8][4];
#pragma unroll
        for (int nj = 0; nj < 8; nj++)
#pragma unroll
            for (int tt = 0; tt < 4; tt++) o[nj][tt] = 0.f;
        float lsum0 = 0.f, lsum1 = 0.f;
        const int qg0 = qt * 128 + wid * 16 + g;

        for (int kt = 0; kt < NS / 64; kt++) {
            CP_WAIT0();
            __syncthreads();             // publishes stage kt; frees buf (kt+1)&1
            if (kt < NS / 64 - 1) {
                uint32_t sbase = sb + FSTG + (uint32_t)(((kt + 1) & 1) * 32768);
#pragma unroll
                for (int u = 0; u < 2; u++) {
                    int idx = u * 256 + tid;
                    int r = idx >> 3, c = idx & 7;
                    uint32_t bo = SW128((uint32_t)(r * 128 + c * 16));
                    size_t go = kvbase + (size_t)((kt + 1) * 64 + r) * NDK + c * 8;
                    cp_async16(sbase + FKHI + bo, g_Khi + go);
                    cp_async16(sbase + FKLO + bo, g_Klo + go);
                    cp_async16(sbase + FVHI + bo, g_Vhi + go);
                    cp_async16(sbase + FVLO + bo, g_Vlo + go);
                }
                CP_COMMIT();
            }

            const uint32_t st = sb + FSTG + (uint32_t)((kt & 1) * 32768);

            // QK^T
            float sc[8][4];
#pragma unroll
            for (int nj = 0; nj < 8; nj++)
#pragma unroll
                for (int tt = 0; tt < 4; tt++) sc[nj][tt] = 0.f;

#pragma unroll
            for (int kk = 0; kk < 4; kk++) {
                uint32_t qh4[4], ql4[4];
                uint32_t qo = SW128(aRow * 128 + (uint32_t)(kk * 32) + aKb);
                ldm_x4(qh4[0], qh4[1], qh4[2], qh4[3], sb + FQHI + qo);
                ldm_x4(ql4[0], ql4[1], ql4[2], ql4[3], sb + FQLO + qo);
#pragma unroll
                for (int njp = 0; njp < 4; njp++) {
                    uint32_t bo = SW128((bRow + njp * 16) * 128 + (uint32_t)(kk * 32) + bKb);
                    uint32_t bh4[4], bl4[4];
                    ldm_x4(bh4[0], bh4[1], bh4[2], bh4[3], st + FKHI + bo);
                    ldm_x4(bl4[0], bl4[1], bl4[2], bl4[3], st + FKLO + bo);
                    mma16816(sc[2 * njp + 0], qh4, &bh4[0]);
                    mma16816(sc[2 * njp + 1], qh4, &bh4[2]);
                    mma16816(sc[2 * njp + 0], ql4, &bh4[0]);
                    mma16816(sc[2 * njp + 1], ql4, &bh4[2]);
                    mma16816(sc[2 * njp + 0], qh4, &bl4[0]);
                    mma16816(sc[2 * njp + 1], qh4, &bl4[2]);
                }
            }

            // mask (bitmap) + fixed-max exp2 softmax
            uint2 w0 = *(const uint2*)(g_maskbits + (size_t)qg0 * 32 + kt);
            uint2 w1 = *(const uint2*)(g_maskbits + (size_t)(qg0 + 8) * 32 + kt);
            float rs0 = 0.f, rs1 = 0.f;
#pragma unroll
            for (int nj = 0; nj < 8; nj++) {
                unsigned s0 = (nj < 4) ? w0.x : w0.y;
                unsigned s1 = (nj < 4) ? w1.x : w1.y;
                int sh = ((nj & 3) << 3) + (tg << 1);
                unsigned b0 = s0 >> sh, b1 = s1 >> sh;
                float p0 = ex2f((b0 & 1) ? fmaf(sc[nj][0], EXP_K2, -EXP_C2) : -1e9f);
                float p1 = ex2f((b0 & 2) ? fmaf(sc[nj][1], EXP_K2, -EXP_C2) : -1e9f);
                float p2 = ex2f((b1 & 1) ? fmaf(sc[nj][2], EXP_K2, -EXP_C2) : -1e9f);
                float p3 = ex2f((b1 & 2) ? fmaf(sc[nj][3], EXP_K2, -EXP_C2) : -1e9f);
                sc[nj][0] = p0; sc[nj][1] = p1;
                sc[nj][2] = p2; sc[nj][3] = p3;
                rs0 += p0 + p1;
                rs1 += p2 + p3;
            }
            rs0 += __shfl_xor_sync(0xffffffffu, rs0, 1);
            rs0 += __shfl_xor_sync(0xffffffffu, rs0, 2);
            rs1 += __shfl_xor_sync(0xffffffffu, rs1, 1);
            rs1 += __shfl_xor_sync(0xffffffffu, rs1, 2);
            lsum0 += rs0;
            lsum1 += rs1;

            // P*V
#pragma unroll
            for (int kk = 0; kk < 4; kk++) {
                uint32_t ph[4], pl[4];
                split_pair(sc[2 * kk][0],     sc[2 * kk][1],     ph[0], pl[0]);
                split_pair(sc[2 * kk][2],     sc[2 * kk][3],     ph[1], pl[1]);
                split_pair(sc[2 * kk + 1][0], sc[2 * kk + 1][1], ph[2], pl[2]);
                split_pair(sc[2 * kk + 1][2], sc[2 * kk + 1][3], ph[3], pl[3]);
#pragma unroll
                for (int njp = 0; njp < 4; njp++) {
                    uint32_t bo = SW128((uint32_t)(kk * 16 + vRow) * 128 +
                                        (uint32_t)(njp * 32) + vNb);
                    uint32_t vh4[4], vl4[4];
                    ldm_x4t(vh4[0], vh4[1], vh4[2], vh4[3], st + FVHI + bo);
                    ldm_x4t(vl4[0], vl4[1], vl4[2], vl4[3], st + FVLO + bo);
                    mma16816(o[2 * njp + 0], ph, &vh4[0]);
                    mma16816(o[2 * njp + 1], ph, &vh4[2]);
                    mma16816(o[2 * njp + 0], pl, &vh4[0]);
                    mma16816(o[2 * njp + 1], pl, &vh4[2]);
                    mma16816(o[2 * njp + 0], ph, &vl4[0]);
                    mma16816(o[2 * njp + 1], ph, &vl4[2]);
                }
            }
        }

        // epilogue: write split bf16 attention output into activation slot 0
        float inv0 = 1.f / lsum0, inv1 = 1.f / lsum1;
        const size_t row0 = (size_t)(b * NS + qg0) * ND;
        const size_t row1 = row0 + (size_t)8 * ND;
#pragma unroll
        for (int njd = 0; njd < 8; njd++) {
            int col = h * NDK + njd * 8 + tg * 2;
            uint32_t hi, lo;
            split_pair(o[njd][0] * inv0, o[njd][1] * inv0, hi, lo);
            *(uint32_t*)(g_Ahi + row0 + col) = hi;
            *(uint32_t*)(g_Alo + row0 + col) = lo;
            split_pair(o[njd][2] * inv1, o[njd][3] * inv1, hi, lo);
            *(uint32_t*)(g_Ahi + row1 + col) = hi;
            *(uint32_t*)(g_Alo + row1 + col) = lo;
        }
    }
}

// ---------------------------------------------------------------------------
extern "C" void kernel_launch(void* const* d_in, const int* in_sizes, int n_in,
                              void* d_out, int out_size)
{
    const float* q    = (const float*)d_in[0];
    const float* k    = (const float*)d_in[1];
    const float* v    = (const float*)d_in[2];
    const int*   mask = (const int*)d_in[3];
    const float* w_q  = (const float*)d_in[4];
    const float* b_q  = (const float*)d_in[5];
    const float* w_k  = (const float*)d_in[6];
    const float* b_k  = (const float*)d_in[7];
    const float* w_v  = (const float*)d_in[8];
    const float* b_v  = (const float*)d_in[9];
    const float* w_o  = (const float*)d_in[10];
    const float* b_o  = (const float*)d_in[11];

    cudaFuncSetAttribute(gemm_tc, cudaFuncAttributeMaxDynamicSharedMemorySize, GEMM_SMEM);
    cudaFuncSetAttribute(flash_mma, cudaFuncAttributeMaxDynamicSharedMemorySize, FLASH_SMEM);

    // fused preprocessing (mask bitmap + counter reset + all splits)
    prep<<<PREP_BLOCKS, 256>>>(mask, q, k, v, w_q, w_k, w_v, w_o);

    dim3 qkvgrid(ND / 128, NM / 128, 3);        // (8, 64, 3)
    gemm_tc<<<qkvgrid, 512, GEMM_SMEM>>>(b_q, b_k, b_v, nullptr, 1);

    flash_mma<<<296, 256, FLASH_SMEM>>>();      // persistent: 2 CTAs/SM

    dim3 ogrid(ND / 128, NM / 128, 1);          // (8, 64)
    gemm_tc<<<ogrid, 512, GEMM_SMEM>>>(b_o, b_o, b_o, (float*)d_out, 0);
}

// round 17
// speedup vs baseline: 1.0855x; 1.0028x over previous
#include <cuda_runtime.h>
#include <cuda_bf16.h>
#include <cstdint>

typedef unsigned long long u64;

// Problem constants
#define NB 4
#define NS 2048
#define ND 1024
#define NH 16
#define NDK 64
#define NM (NB * NS)   // 8192 rows

// ---------------------------------------------------------------------------
// Scratch (device globals: allocation-free)
// ---------------------------------------------------------------------------
__device__ __align__(16) __nv_bfloat16 g_Ahi[3 * NM * ND];
__device__ __align__(16) __nv_bfloat16 g_Alo[3 * NM * ND];
__device__ __align__(16) __nv_bfloat16 g_Whi[4 * ND * ND];
__device__ __align__(16) __nv_bfloat16 g_Wlo[4 * ND * ND];
__device__ __align__(16) __nv_bfloat16 g_Qhi[NB * NH * NS * NDK];  // [B,H,S,dk]
__device__ __align__(16) __nv_bfloat16 g_Qlo[NB * NH * NS * NDK];
__device__ __align__(16) __nv_bfloat16 g_Khi[NB * NH * NS * NDK];
__device__ __align__(16) __nv_bfloat16 g_Klo[NB * NH * NS * NDK];
__device__ __align__(16) __nv_bfloat16 g_Vhi[NB * NH * NS * NDK];
__device__ __align__(16) __nv_bfloat16 g_Vlo[NB * NH * NS * NDK];
__device__ __align__(16) u64 g_maskbits[NS * NS / 64];    // bit-packed mask
__device__ int g_tile_counter;                            // flash work queue
__device__ int g_gemm_ctr1;                               // QKV gemm work queue
__device__ int g_gemm_ctr2;                               // O gemm work queue

// ---------------------------------------------------------------------------
// Helpers
// ---------------------------------------------------------------------------
__device__ __forceinline__ uint32_t smem_u32(const void* p) {
    uint32_t a;
    asm("{ .reg .u64 t; cvta.to.shared.u64 t, %1; cvt.u32.u64 %0, t; }" : "=r"(a) : "l"(p));
    return a;
}
#define SW128(bo) ((bo) ^ (((bo) >> 3) & 0x70))

__device__ __forceinline__ void ldm_x4(uint32_t& r0, uint32_t& r1, uint32_t& r2,
                                       uint32_t& r3, uint32_t addr) {
    asm volatile("ldmatrix.sync.aligned.m8n8.x4.shared.b16 {%0,%1,%2,%3}, [%4];"
                 : "=r"(r0), "=r"(r1), "=r"(r2), "=r"(r3) : "r"(addr));
}
__device__ __forceinline__ void ldm_x4t(uint32_t& r0, uint32_t& r1, uint32_t& r2,
                                        uint32_t& r3, uint32_t addr) {
    asm volatile("ldmatrix.sync.aligned.m8n8.x4.trans.shared.b16 {%0,%1,%2,%3}, [%4];"
                 : "=r"(r0), "=r"(r1), "=r"(r2), "=r"(r3) : "r"(addr));
}
__device__ __forceinline__ void mma16816(float* d, const uint32_t* a, const uint32_t* b) {
    asm volatile("mma.sync.aligned.m16n8k16.row.col.f32.bf16.bf16.f32 "
                 "{%0,%1,%2,%3}, {%4,%5,%6,%7}, {%8,%9}, {%0,%1,%2,%3};"
                 : "+f"(d[0]), "+f"(d[1]), "+f"(d[2]), "+f"(d[3])
                 : "r"(a[0]), "r"(a[1]), "r"(a[2]), "r"(a[3]), "r"(b[0]), "r"(b[1]));
}

__device__ __forceinline__ void cp_async16(uint32_t s, const void* g) {
    asm volatile("{ .reg .u64 gg; cvta.to.global.u64 gg, %1; "
                 "cp.async.cg.shared.global [%0], [gg], 16; }"
                 :: "r"(s), "l"(g) : "memory");
}
#define CP_COMMIT() asm volatile("cp.async.commit_group;" ::: "memory")
#define CP_WAIT1()  asm volatile("cp.async.wait_group 1;" ::: "memory")
#define CP_WAIT0()  asm volatile("cp.async.wait_group 0;" ::: "memory")

__device__ __forceinline__ float ex2f(float x) {
    float r;
    asm("ex2.approx.f32 %0, %1;" : "=f"(r) : "f"(x));
    return r;
}

// split fp32 pair -> packed bf16 hi pair + bf16 residual pair
__device__ __forceinline__ void split_pair(float a, float b, uint32_t& hi, uint32_t& lo) {
    __nv_bfloat16 ha = __float2bfloat16(a), hb = __float2bfloat16(b);
    __nv_bfloat16 la = __float2bfloat16(a - __bfloat162float(ha));
    __nv_bfloat16 lb = __float2bfloat16(b - __bfloat162float(hb));
    __nv_bfloat162 H(ha, hb), L(la, lb);
    hi = *reinterpret_cast<uint32_t*>(&H);
    lo = *reinterpret_cast<uint32_t*>(&L);
}

// split 8 contiguous fp32 -> 16B hi plane + 16B lo plane
__device__ __forceinline__ void split8(const float* __restrict__ src,
                                       __nv_bfloat16* dhi, __nv_bfloat16* dlo, size_t i)
{
    float4 v0 = *(const float4*)(src + i);
    float4 v1 = *(const float4*)(src + i + 4);
    uint4 H, L;
    split_pair(v0.x, v0.y, H.x, L.x);
    split_pair(v0.z, v0.w, H.y, L.y);
    split_pair(v1.x, v1.y, H.z, L.z);
    split_pair(v1.z, v1.w, H.w, L.w);
    *(uint4*)(dhi + i) = H;
    *(uint4*)(dlo + i) = L;
}

// ---------------------------------------------------------------------------
// Fused preprocess: ONE launch.
// blocks [0,256):        mask_pack (+ all work-queue counter resets)
// blocks [256,12544):    split_act (3 slots x 4096 blocks, 8 elems/thread)
// blocks [12544,14592):  split_wgt (4 slots x 512 blocks, 8 elems/thread)
// ---------------------------------------------------------------------------
#define PREP_BLOCKS (256 + 3 * 4096 + 4 * 512)   // 14592

__global__ __launch_bounds__(256) void prep(
    const int* __restrict__ mask,
    const float* __restrict__ a0, const float* __restrict__ a1,
    const float* __restrict__ a2,
    const float* __restrict__ w0, const float* __restrict__ w1,
    const float* __restrict__ w2, const float* __restrict__ w3)
{
    const int bid = blockIdx.x;
    const int tid = threadIdx.x;
    if (bid < 256) {
        if (bid == 0 && tid == 0) {
            g_tile_counter = 0;
            g_gemm_ctr1 = 0;
            g_gemm_ctr2 = 0;
        }
        int w = bid * 256 + tid;     // 0 .. 65535
        const int4* src = (const int4*)(mask + (size_t)w * 64);
        u64 bits = 0;
#pragma unroll
        for (int q = 0; q < 16; q++) {
            int4 v = src[q];
            bits |= ((u64)(v.x != 0) << (q * 4 + 0)) | ((u64)(v.y != 0) << (q * 4 + 1))
                  | ((u64)(v.z != 0) << (q * 4 + 2)) | ((u64)(v.w != 0) << (q * 4 + 3));
        }
        g_maskbits[w] = bits;
    } else if (bid < 12544) {
        int rel = bid - 256;
        int slot = rel >> 12;                    // /4096
        const float* src = (slot == 0) ? a0 : (slot == 1) ? a1 : a2;
        size_t base = (size_t)slot * NM * ND;
        size_t i = ((size_t)(rel & 4095) * 256 + tid) * 8;
        split8(src, g_Ahi + base, g_Alo + base, i);
    } else {
        int rel = bid - 12544;
        int slot = rel >> 9;                     // /512
        const float* src = (slot == 0) ? w0 : (slot == 1) ? w1 : (slot == 2) ? w2 : w3;
        size_t base = (size_t)slot * ND * ND;
        size_t i = ((size_t)(rel & 511) * 256 + tid) * 8;
        split8(src, g_Whi + base, g_Wlo + base, i);
    }
}

// ---------------------------------------------------------------------------
// PERSISTENT mma.sync GEMM: 148 CTAs x 512 threads, work queue over tiles.
// Per tile: 128x128 output, 3-stage cp.async pipeline, ONE barrier per chunk.
// Warp grid 4(m) x 4(n), warp tile 32x32 (proven R8 math).
// base_mode 1: 1536 tiles (QKV, z = t/512); base_mode 0: 512 tiles (O proj).
// Tile decode keeps bn fastest -> consecutive tiles share A rows in L2.
// ---------------------------------------------------------------------------
#define GOFF_AHI 0
#define GOFF_ALO 16384
#define GOFF_WHI 32768
#define GOFF_WLO 49152
#define GSTAGE   65536
#define GEMM_SMEM (3 * GSTAGE)   // 196608

__global__ __launch_bounds__(512) void gemm_tc(
    const float* __restrict__ bias0, const float* __restrict__ bias1,
    const float* __restrict__ bias2, float* __restrict__ Cp, int base_mode)
{
    extern __shared__ __align__(1024) char smem[];
    __shared__ int s_tile;
    const uint32_t sb = smem_u32(smem);
    const int tid = threadIdx.x;
    const int wid = tid >> 5;
    const int lane = tid & 31;
    const int wm = wid >> 2;
    const int wn = wid & 3;
    const int n_tiles = (base_mode == 1) ? 1536 : 512;
    int* ctr = (base_mode == 1) ? &g_gemm_ctr1 : &g_gemm_ctr2;

    const uint32_t aRow = (uint32_t)(wm * 32 + (lane & 15));
    const uint32_t aKb  = (uint32_t)((lane >> 4) << 4);
    const uint32_t bRow = (uint32_t)(wn * 32 + (lane & 7) + ((lane >> 4) & 1) * 8);
    const uint32_t bKb  = (uint32_t)(((lane >> 3) & 1) << 4);
    const int g = lane >> 2, tg = lane & 3;

    for (;;) {
        __syncthreads();   // prior tile fully consumed (smem safe) + s_tile reuse
        if (tid == 0) s_tile = atomicAdd(ctr, 1);
        __syncthreads();
        const int t = s_tile;
        if (t >= n_tiles) break;

        const int z = t >> 9;            // 0..2 (QKV) or 0 (O)
        const int rem = t & 511;
        const int bn = (rem & 7) * 128;
        const int bm = (rem >> 3) * 128;
        const int mode = (base_mode == 0) ? 0 : 1 + z;
        const float* bias = (z == 0) ? bias0 : (z == 1) ? bias1 : bias2;

        const int aslot = (mode == 0) ? 0 : mode - 1;
        const int wslot = (mode == 0) ? 3 : mode - 1;
        const __nv_bfloat16* Ahi = g_Ahi + (size_t)aslot * NM * ND;
        const __nv_bfloat16* Alo = g_Alo + (size_t)aslot * NM * ND;
        const __nv_bfloat16* Whi = g_Whi + (size_t)wslot * ND * ND;
        const __nv_bfloat16* Wlo = g_Wlo + (size_t)wslot * ND * ND;

        const __nv_bfloat16* srcs[4] = {Ahi, Alo, Whi, Wlo};
        const int row0[4] = {bm, bm, bn, bn};
        const uint32_t toff[4] = {GOFF_AHI, GOFF_ALO, GOFF_WHI, GOFF_WLO};

        float acc[2][4][4];
#pragma unroll
        for (int mi = 0; mi < 2; mi++)
#pragma unroll
            for (int c = 0; c < 4; c++)
#pragma unroll
                for (int tt = 0; tt < 4; tt++) acc[mi][c][tt] = 0.f;

        auto load_stage = [&](int kc) {
            const int k0 = kc * 64;
            const uint32_t sbase = sb + (uint32_t)((kc % 3) * GSTAGE);
#pragma unroll
            for (int tb = 0; tb < 4; tb++) {
#pragma unroll
                for (int u = 0; u < 2; u++) {
                    int idx = u * 512 + tid;
                    int r = idx >> 3, c = idx & 7;
                    uint32_t bo = (uint32_t)(r * 128 + c * 16);
                    cp_async16(sbase + toff[tb] + SW128(bo),
                               srcs[tb] + (size_t)(row0[tb] + r) * ND + k0 + c * 8);
                }
            }
        };

        load_stage(0); CP_COMMIT();
        load_stage(1); CP_COMMIT();

        for (int kc = 0; kc < 16; kc++) {
            if (kc < 14) CP_WAIT1(); else CP_WAIT0();
            __syncthreads();               // publishes stage kc; frees buf (kc+2)%3
            if (kc < 14) { load_stage(kc + 2); CP_COMMIT(); }

            const uint32_t stage = sb + (uint32_t)((kc % 3) * GSTAGE);
#pragma unroll
            for (int ks = 0; ks < 4; ks++) {
                uint32_t ah[2][4], al[2][4];
#pragma unroll
                for (int mi = 0; mi < 2; mi++) {
                    uint32_t off = SW128((aRow + mi * 16) * 128 + (uint32_t)(ks * 32) + aKb);
                    ldm_x4(ah[mi][0], ah[mi][1], ah[mi][2], ah[mi][3], stage + GOFF_AHI + off);
                    ldm_x4(al[mi][0], al[mi][1], al[mi][2], al[mi][3], stage + GOFF_ALO + off);
                }
                uint32_t bh[2][4], bl[2][4];
#pragma unroll
                for (int nj = 0; nj < 2; nj++) {
                    uint32_t off = SW128((bRow + nj * 16) * 128 + (uint32_t)(ks * 32) + bKb);
                    ldm_x4(bh[nj][0], bh[nj][1], bh[nj][2], bh[nj][3], stage + GOFF_WHI + off);
                    ldm_x4(bl[nj][0], bl[nj][1], bl[nj][2], bl[nj][3], stage + GOFF_WLO + off);
                }
#pragma unroll
                for (int mi = 0; mi < 2; mi++)
#pragma unroll
                    for (int nj = 0; nj < 2; nj++) {
                        mma16816(acc[mi][nj * 2 + 0], ah[mi], &bh[nj][0]);
                        mma16816(acc[mi][nj * 2 + 1], ah[mi], &bh[nj][2]);
                    }
#pragma unroll
                for (int mi = 0; mi < 2; mi++)
#pragma unroll
                    for (int nj = 0; nj < 2; nj++) {
                        mma16816(acc[mi][nj * 2 + 0], al[mi], &bh[nj][0]);
                        mma16816(acc[mi][nj * 2 + 1], al[mi], &bh[nj][2]);
                    }
#pragma unroll
                for (int mi = 0; mi < 2; mi++)
#pragma unroll
                    for (int nj = 0; nj < 2; nj++) {
                        mma16816(acc[mi][nj * 2 + 0], ah[mi], &bl[nj][0]);
                        mma16816(acc[mi][nj * 2 + 1], ah[mi], &bl[nj][2]);
                    }
            }
        }

        // Epilogue
        __nv_bfloat16 *dHi = nullptr, *dLo = nullptr;
        if (mode == 1) { dHi = g_Qhi; dLo = g_Qlo; }
        else if (mode == 2) { dHi = g_Khi; dLo = g_Klo; }
        else if (mode == 3) { dHi = g_Vhi; dLo = g_Vlo; }

#pragma unroll
        for (int mi = 0; mi < 2; mi++) {
#pragma unroll
            for (int c = 0; c < 4; c++) {
                int n = bn + wn * 32 + c * 8 + tg * 2;
                float bx = bias[n], by = bias[n + 1];
                int m0 = bm + wm * 32 + mi * 16 + g;
#pragma unroll
                for (int half = 0; half < 2; half++) {
                    int m = m0 + half * 8;
                    float ox = acc[mi][c][half * 2 + 0] + bx;
                    float oy = acc[mi][c][half * 2 + 1] + by;
                    if (mode == 0) {
                        *(float2*)(Cp + (size_t)m * ND + n) = make_float2(ox, oy);
                    } else {
                        int bb = m >> 11, ss = m & 2047;
                        int h = n >> 6, dd = n & 63;
                        size_t idx = (((size_t)(bb * NH + h) * NS + ss) * NDK) + dd;
                        uint32_t hi, lo;
                        split_pair(ox, oy, hi, lo);
                        *(uint32_t*)(dHi + idx) = hi;
                        *(uint32_t*)(dLo + idx) = lo;
                    }
                }
            }
        }
    }
}

// ---------------------------------------------------------------------------
// PERSISTENT flash attention on tensor cores (split bf16, 3-MMA).
// 296 CTAs (2/SM), 256 threads; fixed-max exp2 softmax. (R13/R16 proven)
// ---------------------------------------------------------------------------
#define FQHI 0
#define FQLO 16384
#define FSTG 32768
#define FKHI 0
#define FKLO 8192
#define FVHI 16384
#define FVLO 24576
#define FLASH_SMEM (32768 + 2 * 32768)   // 98304
#define N_TILES (NB * NH * (NS / 128))   // 1024

#define EXP_K2 0.18033688011112042f     // 0.125 * log2(e)
#define EXP_C2 23.083120654223414f      // 16 * log2(e)

__global__ __launch_bounds__(256, 2) void flash_mma(void)
{
    extern __shared__ __align__(1024) char fsm[];
    __shared__ int s_tile;
    const uint32_t sb = smem_u32(fsm);
    const int tid = threadIdx.x;
    const int wid = tid >> 5;
    const int lane = tid & 31;
    const int g = lane >> 2, tg = lane & 3;

    // fragment address components (tile-independent)
    const uint32_t aRow = (uint32_t)(wid * 16 + (lane & 15));
    const uint32_t aKb  = (uint32_t)((lane >> 4) << 4);
    const uint32_t bRow = (uint32_t)((lane & 7) + ((lane >> 4) & 1) * 8);
    const uint32_t bKb  = (uint32_t)(((lane >> 3) & 1) << 4);
    const uint32_t vRow = (uint32_t)((lane & 7) + ((lane >> 3) & 1) * 8);   // trans
    const uint32_t vNb  = (uint32_t)(((lane >> 4) & 1) << 4);

    for (;;) {
        __syncthreads();   // prior tile fully consumed (smem safe) + s_tile reuse
        if (tid == 0) s_tile = atomicAdd(&g_tile_counter, 1);
        __syncthreads();
        const int t = s_tile;
        if (t >= N_TILES) break;

        const int qt = t & 15;
        const int h  = (t >> 4) & 15;
        const int b  = t >> 8;

        const size_t kvbase = (size_t)(b * NH + h) * NS * NDK;
        const size_t qbase  = kvbase + (size_t)qt * 128 * NDK;

        // Q tile + first KV stage
#pragma unroll
        for (int u = 0; u < 4; u++) {
            int idx = u * 256 + tid;
            int r = idx >> 3, c = idx & 7;
            uint32_t bo = SW128((uint32_t)(r * 128 + c * 16));
            size_t go = qbase + (size_t)r * NDK + c * 8;
            cp_async16(sb + FQHI + bo, g_Qhi + go);
            cp_async16(sb + FQLO + bo, g_Qlo + go);
        }
#pragma unroll
        for (int u = 0; u < 2; u++) {
            int idx = u * 256 + tid;
            int r = idx >> 3, c = idx & 7;
            uint32_t bo = SW128((uint32_t)(r * 128 + c * 16));
            size_t go = kvbase + (size_t)r * NDK + c * 8;
            cp_async16(sb + FSTG + FKHI + bo, g_Khi + go);
            cp_async16(sb + FSTG + FKLO + bo, g_Klo + go);
            cp_async16(sb + FSTG + FVHI + bo, g_Vhi + go);
            cp_async16(sb + FSTG + FVLO + bo, g_Vlo + go);
        }
        CP_COMMIT();

        float o[8][4];
#pragma unroll
        for (int nj = 0; nj < 8; nj++)
#pragma unroll
            for (int tt = 0; tt < 4; tt++) o[nj][tt] = 0.f;
        float lsum0 = 0.f, lsum1 = 0.f;
        const int qg0 = qt * 128 + wid * 16 + g;

        for (int kt = 0; kt < NS / 64; kt++) {
            CP_WAIT0();
            __syncthreads();             // publishes stage kt; frees buf (kt+1)&1
            if (kt < NS / 64 - 1) {
                uint32_t sbase = sb + FSTG + (uint32_t)(((kt + 1) & 1) * 32768);
#pragma unroll
                for (int u = 0; u < 2; u++) {
                    int idx = u * 256 + tid;
                    int r = idx >> 3, c = idx & 7;
                    uint32_t bo = SW128((uint32_t)(r * 128 + c * 16));
                    size_t go = kvbase + (size_t)((kt + 1) * 64 + r) * NDK + c * 8;
                    cp_async16(sbase + FKHI + bo, g_Khi + go);
                    cp_async16(sbase + FKLO + bo, g_Klo + go);
                    cp_async16(sbase + FVHI + bo, g_Vhi + go);
                    cp_async16(sbase + FVLO + bo, g_Vlo + go);
                }
                CP_COMMIT();
            }

            const uint32_t st = sb + FSTG + (uint32_t)((kt & 1) * 32768);

            // QK^T
            float sc[8][4];
#pragma unroll
            for (int nj = 0; nj < 8; nj++)
#pragma unroll
                for (int tt = 0; tt < 4; tt++) sc[nj][tt] = 0.f;

#pragma unroll
            for (int kk = 0; kk < 4; kk++) {
                uint32_t qh4[4], ql4[4];
                uint32_t qo = SW128(aRow * 128 + (uint32_t)(kk * 32) + aKb);
                ldm_x4(qh4[0], qh4[1], qh4[2], qh4[3], sb + FQHI + qo);
                ldm_x4(ql4[0], ql4[1], ql4[2], ql4[3], sb + FQLO + qo);
#pragma unroll
                for (int njp = 0; njp < 4; njp++) {
                    uint32_t bo = SW128((bRow + njp * 16) * 128 + (uint32_t)(kk * 32) + bKb);
                    uint32_t bh4[4], bl4[4];
                    ldm_x4(bh4[0], bh4[1], bh4[2], bh4[3], st + FKHI + bo);
                    ldm_x4(bl4[0], bl4[1], bl4[2], bl4[3], st + FKLO + bo);
                    mma16816(sc[2 * njp + 0], qh4, &bh4[0]);
                    mma16816(sc[2 * njp + 1], qh4, &bh4[2]);
                    mma16816(sc[2 * njp + 0], ql4, &bh4[0]);
                    mma16816(sc[2 * njp + 1], ql4, &bh4[2]);
                    mma16816(sc[2 * njp + 0], qh4, &bl4[0]);
                    mma16816(sc[2 * njp + 1], qh4, &bl4[2]);
                }
            }

            // mask (bitmap) + fixed-max exp2 softmax
            uint2 w0 = *(const uint2*)(g_maskbits + (size_t)qg0 * 32 + kt);
            uint2 w1 = *(const uint2*)(g_maskbits + (size_t)(qg0 + 8) * 32 + kt);
            float rs0 = 0.f, rs1 = 0.f;
#pragma unroll
            for (int nj = 0; nj < 8; nj++) {
                unsigned s0 = (nj < 4) ? w0.x : w0.y;
                unsigned s1 = (nj < 4) ? w1.x : w1.y;
                int sh = ((nj & 3) << 3) + (tg << 1);
                unsigned b0 = s0 >> sh, b1 = s1 >> sh;
                float p0 = ex2f((b0 & 1) ? fmaf(sc[nj][0], EXP_K2, -EXP_C2) : -1e9f);
                float p1 = ex2f((b0 & 2) ? fmaf(sc[nj][1], EXP_K2, -EXP_C2) : -1e9f);
                float p2 = ex2f((b1 & 1) ? fmaf(sc[nj][2], EXP_K2, -EXP_C2) : -1e9f);
                float p3 = ex2f((b1 & 2) ? fmaf(sc[nj][3], EXP_K2, -EXP_C2) : -1e9f);
                sc[nj][0] = p0; sc[nj][1] = p1;
                sc[nj][2] = p2; sc[nj][3] = p3;
                rs0 += p0 + p1;
                rs1 += p2 + p3;
            }
            rs0 += __shfl_xor_sync(0xffffffffu, rs0, 1);
            rs0 += __shfl_xor_sync(0xffffffffu, rs0, 2);
            rs1 += __shfl_xor_sync(0xffffffffu, rs1, 1);
            rs1 += __shfl_xor_sync(0xffffffffu, rs1, 2);
            lsum0 += rs0;
            lsum1 += rs1;

            // P*V
#pragma unroll
            for (int kk = 0; kk < 4; kk++) {
                uint32_t ph[4], pl[4];
                split_pair(sc[2 * kk][0],     sc[2 * kk][1],     ph[0], pl[0]);
                split_pair(sc[2 * kk][2],     sc[2 * kk][3],     ph[1], pl[1]);
                split_pair(sc[2 * kk + 1][0], sc[2 * kk + 1][1], ph[2], pl[2]);
                split_pair(sc[2 * kk + 1][2], sc[2 * kk + 1][3], ph[3], pl[3]);
#pragma unroll
                for (int njp = 0; njp < 4; njp++) {
                    uint32_t bo = SW128((uint32_t)(kk * 16 + vRow) * 128 +
                                        (uint32_t)(njp * 32) + vNb);
                    uint32_t vh4[4], vl4[4];
                    ldm_x4t(vh4[0], vh4[1], vh4[2], vh4[3], st + FVHI + bo);
                    ldm_x4t(vl4[0], vl4[1], vl4[2], vl4[3], st + FVLO + bo);
                    mma16816(o[2 * njp + 0], ph, &vh4[0]);
                    mma16816(o[2 * njp + 1], ph, &vh4[2]);
                    mma16816(o[2 * njp + 0], pl, &vh4[0]);
                    mma16816(o[2 * njp + 1], pl, &vh4[2]);
                    mma16816(o[2 * njp + 0], ph, &vl4[0]);
                    mma16816(o[2 * njp + 1], ph, &vl4[2]);
                }
            }
        }

        // epilogue: write split bf16 attention output into activation slot 0
        float inv0 = 1.f / lsum0, inv1 = 1.f / lsum1;
        const size_t row0 = (size_t)(b * NS + qg0) * ND;
        const size_t row1 = row0 + (size_t)8 * ND;
#pragma unroll
        for (int njd = 0; njd < 8; njd++) {
            int col = h * NDK + njd * 8 + tg * 2;
            uint32_t hi, lo;
            split_pair(o[njd][0] * inv0, o[njd][1] * inv0, hi, lo);
            *(uint32_t*)(g_Ahi + row0 + col) = hi;
            *(uint32_t*)(g_Alo + row0 + col) = lo;
            split_pair(o[njd][2] * inv1, o[njd][3] * inv1, hi, lo);
            *(uint32_t*)(g_Ahi + row1 + col) = hi;
            *(uint32_t*)(g_Alo + row1 + col) = lo;
        }
    }
}

// ---------------------------------------------------------------------------
extern "C" void kernel_launch(void* const* d_in, const int* in_sizes, int n_in,
                              void* d_out, int out_size)
{
    const float* q    = (const float*)d_in[0];
    const float* k    = (const float*)d_in[1];
    const float* v    = (const float*)d_in[2];
    const int*   mask = (const int*)d_in[3];
    const float* w_q  = (const float*)d_in[4];
    const float* b_q  = (const float*)d_in[5];
    const float* w_k  = (const float*)d_in[6];
    const float* b_k  = (const float*)d_in[7];
    const float* w_v  = (const float*)d_in[8];
    const float* b_v  = (const float*)d_in[9];
    const float* w_o  = (const float*)d_in[10];
    const float* b_o  = (const float*)d_in[11];

    cudaFuncSetAttribute(gemm_tc, cudaFuncAttributeMaxDynamicSharedMemorySize, GEMM_SMEM);
    cudaFuncSetAttribute(flash_mma, cudaFuncAttributeMaxDynamicSharedMemorySize, FLASH_SMEM);

    // fused preprocessing (mask bitmap + counter resets + all splits)
    prep<<<PREP_BLOCKS, 256>>>(mask, q, k, v, w_q, w_k, w_v, w_o);

    // persistent QKV projections (work queue, no wave-quantization tail)
    gemm_tc<<<148, 512, GEMM_SMEM>>>(b_q, b_k, b_v, nullptr, 1);

    flash_mma<<<296, 256, FLASH_SMEM>>>();      // persistent: 2 CTAs/SM

    // persistent output projection
    gemm_tc<<<148, 512, GEMM_SMEM>>>(b_o, b_o, b_o, (float*)d_out, 0);
}